// round 3
// baseline (speedup 1.0000x reference)
#include <cuda_runtime.h>
#include <cuda_bf16.h>
#include <math.h>

#define NN 50000
#define EE 1600000
#define FIN 128
#define HID 256
#define NC 40

#define SCAN_NB 100
#define SCAN_CH 500   // SCAN_NB * SCAN_CH == NN

typedef unsigned long long ull;

// ---------------- scratch (device globals; no allocation) ----------------
__device__ float g_deg[NN];
__device__ float g_inv[NN];
__device__ int   g_cnt[NN];
__device__ int   g_rowstart[NN + 1];
__device__ int   g_cursor[NN];
__device__ int   g_partial[SCAN_NB];
__device__ int   g_blockoff[SCAN_NB];
__device__ int   g_eidx[EE];
__device__ float g_ecoef[EE];
__device__ float g_aggx[(size_t)NN * FIN];
__device__ float g_h[(size_t)NN * HID];
__device__ float g_a[(size_t)NN * HID];

// ---------------- f32x2 helpers ----------------
__device__ __forceinline__ ull pk2(float a, float b) {
    ull r; asm("mov.b64 %0,{%1,%2};" : "=l"(r) : "f"(a), "f"(b)); return r;
}
__device__ __forceinline__ void upk2(ull v, float& a, float& b) {
    asm("mov.b64 {%0,%1},%2;" : "=f"(a), "=f"(b) : "l"(v));
}
__device__ __forceinline__ void ffma2(ull& d, ull a, ull b) {
    asm("fma.rn.f32x2 %0,%1,%2,%0;" : "+l"(d) : "l"(a), "l"(b));
}

// ---------------- graph preprocessing ----------------
__global__ void init_kernel(float* deg, int* cnt) {
    int i = blockIdx.x * blockDim.x + threadIdx.x;
    if (i < NN) { deg[i] = 1.0f; cnt[i] = 0; }   // self-loop in degree
}

__global__ void count_kernel(const int* __restrict__ dst, float* deg, int* cnt) {
    int e = blockIdx.x * blockDim.x + threadIdx.x;
    if (e < EE) {
        int d = dst[e];
        atomicAdd(&deg[d], 1.0f);
        atomicAdd(&cnt[d], 1);
    }
}

__global__ void inv_kernel(const float* __restrict__ deg, float* inv) {
    int i = blockIdx.x * blockDim.x + threadIdx.x;
    if (i < NN) inv[i] = rsqrtf(deg[i]);
}

// phase 1: per-block sums of cnt chunks
__global__ void scan_p1(const int* __restrict__ cnt, int* partial) {
    __shared__ int ws[8];
    int b = blockIdx.x, tid = threadIdx.x;
    int base = b * SCAN_CH;
    int s = 0;
    for (int i = tid; i < SCAN_CH; i += 256) s += cnt[base + i];
    #pragma unroll
    for (int o = 16; o > 0; o >>= 1) s += __shfl_xor_sync(0xFFFFFFFFu, s, o);
    if ((tid & 31) == 0) ws[tid >> 5] = s;
    __syncthreads();
    if (tid == 0) {
        int t = 0;
        #pragma unroll
        for (int j = 0; j < 8; j++) t += ws[j];
        partial[b] = t;
    }
}

// phase 2: warp-cooperative exclusive scan of the 100 partials
__global__ void scan_p2(const int* __restrict__ partial, int* blockoff, int* rowstart) {
    __shared__ int chunk_tot[4];
    int lane = threadIdx.x & 31;
    // 4 chunks of 32 (last chunk padded)
    int vals[4], pref[4];
    #pragma unroll
    for (int c = 0; c < 4; c++) {
        int i = c * 32 + lane;
        int v = (i < SCAN_NB) ? partial[i] : 0;
        vals[c] = v;
        int x = v;
        #pragma unroll
        for (int o = 1; o < 32; o <<= 1) {
            int t = __shfl_up_sync(0xFFFFFFFFu, x, o);
            if (lane >= o) x += t;
        }
        pref[c] = x - v;   // exclusive within chunk
        if (lane == 31) chunk_tot[c] = x;
    }
    __syncwarp();
    int base = 0;
    #pragma unroll
    for (int c = 0; c < 4; c++) {
        int i = c * 32 + lane;
        if (i < SCAN_NB) blockoff[i] = base + pref[c];
        base += chunk_tot[c];
    }
    if (lane == 0) rowstart[NN] = base;
}

// phase 3: per-block local exclusive scan + offset
__global__ void scan_p3(const int* __restrict__ cnt, const int* __restrict__ blockoff,
                        int* rowstart, int* cursor) {
    __shared__ int ws[8];
    __shared__ int s_run, s_tot;
    int b = blockIdx.x, tid = threadIdx.x, lane = tid & 31, w = tid >> 5;
    if (tid == 0) s_run = blockoff[b];
    __syncthreads();
    int cbase = b * SCAN_CH;
    for (int base = 0; base < SCAN_CH; base += 256) {
        int li = base + tid;
        int v = (li < SCAN_CH) ? cnt[cbase + li] : 0;
        int x = v;
        #pragma unroll
        for (int o = 1; o < 32; o <<= 1) {
            int t = __shfl_up_sync(0xFFFFFFFFu, x, o);
            if (lane >= o) x += t;
        }
        if (lane == 31) ws[w] = x;
        __syncthreads();
        if (tid == 0) {
            int s = 0;
            #pragma unroll
            for (int j = 0; j < 8; j++) { int t = ws[j]; ws[j] = s; s += t; }
            s_tot = s;
        }
        __syncthreads();
        int excl = s_run + ws[w] + x - v;
        if (li < SCAN_CH) { rowstart[cbase + li] = excl; cursor[cbase + li] = excl; }
        __syncthreads();
        if (tid == 0) s_run += s_tot;
        __syncthreads();
    }
}

__global__ void fill_kernel(const int* __restrict__ src, const int* __restrict__ dst,
                            const float* __restrict__ inv,
                            int* cursor, int* eidx, float* ecoef) {
    int e = blockIdx.x * blockDim.x + threadIdx.x;
    if (e < EE) {
        int s = src[e], d = dst[e];
        int p = atomicAdd(&cursor[d], 1);
        eidx[p] = s;
        ecoef[p] = inv[s] * inv[d];
    }
}

// ---------------- SpMM aggregation (vectorized): one warp per 128 columns ----------------
// F must be a multiple of 128; CPW = F/128 warps per node.
template <int F, int RELU, int BIAS>
__global__ void agg_vec_kernel(const float* __restrict__ hin, float* __restrict__ out,
                               const int* __restrict__ rowstart,
                               const int* __restrict__ eidx, const float* __restrict__ ecoef,
                               const float* __restrict__ inv, const float* __restrict__ bias) {
    const int CPW = F / 128;
    int gwid = (blockIdx.x * blockDim.x + threadIdx.x) >> 5;
    int lane = threadIdx.x & 31;
    int node = gwid / CPW;
    int part = gwid - node * CPW;
    if (node >= NN) return;
    int col = part * 128 + lane * 4;

    float sn = inv[node]; sn *= sn;
    float4 a = *(const float4*)(hin + (size_t)node * F + col);
    a.x *= sn; a.y *= sn; a.z *= sn; a.w *= sn;

    int j = rowstart[node], end = rowstart[node + 1];
    for (; j + 1 < end; j += 2) {
        int s0 = __ldg(eidx + j), s1 = __ldg(eidx + j + 1);
        float c0 = __ldg(ecoef + j), c1 = __ldg(ecoef + j + 1);
        float4 v0 = *(const float4*)(hin + (size_t)s0 * F + col);
        float4 v1 = *(const float4*)(hin + (size_t)s1 * F + col);
        a.x = fmaf(c0, v0.x, a.x); a.y = fmaf(c0, v0.y, a.y);
        a.z = fmaf(c0, v0.z, a.z); a.w = fmaf(c0, v0.w, a.w);
        a.x = fmaf(c1, v1.x, a.x); a.y = fmaf(c1, v1.y, a.y);
        a.z = fmaf(c1, v1.z, a.z); a.w = fmaf(c1, v1.w, a.w);
    }
    if (j < end) {
        int s0 = __ldg(eidx + j);
        float c0 = __ldg(ecoef + j);
        float4 v0 = *(const float4*)(hin + (size_t)s0 * F + col);
        a.x = fmaf(c0, v0.x, a.x); a.y = fmaf(c0, v0.y, a.y);
        a.z = fmaf(c0, v0.z, a.z); a.w = fmaf(c0, v0.w, a.w);
    }
    if (BIAS) {
        const float4 bv = *(const float4*)(bias + col);
        a.x += bv.x; a.y += bv.y; a.z += bv.z; a.w += bv.w;
    }
    if (RELU) {
        a.x = fmaxf(a.x, 0.f); a.y = fmaxf(a.y, 0.f);
        a.z = fmaxf(a.z, 0.f); a.w = fmaxf(a.w, 0.f);
    }
    *(float4*)(out + (size_t)node * F + col) = a;
}

// scalar agg for F=40 (one warp per node)
template <int F, int RELU, int BIAS>
__global__ void agg_kernel(const float* __restrict__ hin, float* __restrict__ out,
                           const int* __restrict__ rowstart,
                           const int* __restrict__ eidx, const float* __restrict__ ecoef,
                           const float* __restrict__ inv, const float* __restrict__ bias) {
    int node = (blockIdx.x * blockDim.x + threadIdx.x) >> 5;
    int lane = threadIdx.x & 31;
    if (node >= NN) return;
    const int KC = (F + 31) / 32;
    float acc[KC];
    float sn = inv[node]; sn *= sn;
    const float* hrow = hin + (size_t)node * F;
    #pragma unroll
    for (int k = 0; k < KC; k++) {
        int c = lane + 32 * k;
        acc[k] = (c < F) ? hrow[c] * sn : 0.0f;
    }
    int beg = rowstart[node], end = rowstart[node + 1];
    for (int j = beg; j < end; j++) {
        int s = __ldg(eidx + j);
        float cf = __ldg(ecoef + j);
        const float* hs = hin + (size_t)s * F;
        #pragma unroll
        for (int k = 0; k < KC; k++) {
            int c = lane + 32 * k;
            if (c < F) acc[k] = fmaf(cf, __ldg(hs + c), acc[k]);
        }
    }
    float* orow = out + (size_t)node * F;
    #pragma unroll
    for (int k = 0; k < KC; k++) {
        int c = lane + 32 * k;
        if (c < F) {
            float v = acc[k] + (BIAS ? bias[c] : 0.0f);
            if (RELU) v = fmaxf(v, 0.0f);
            orow[c] = v;
        }
    }
}

// ---------------- f32x2 tiled GEMM: C[M,Nn] = A[M,K] @ W[K,Nn] (+bias)(+relu) ----------------
// BM=128, BN=128, BK=16, 256 threads, 8x8 micro-tile as 8x4 packed f32x2
template <int RELU, int BIAS>
__global__ void __launch_bounds__(256, 2)
gemm_f2_kernel(const float* __restrict__ A, const float* __restrict__ W,
               const float* __restrict__ bias, float* __restrict__ C,
               int M, int K, int Nn) {
    __shared__ __align__(16) float As[16][132];
    __shared__ __align__(16) float Bs[16][132];
    int tid = threadIdx.x;
    int m0 = blockIdx.y * 128;
    int n0 = blockIdx.x * 128;
    int tx = tid & 15;    // col group of 8
    int ty = tid >> 4;    // row group of 8
    ull acc[8][4];
    #pragma unroll
    for (int i = 0; i < 8; i++)
        #pragma unroll
        for (int j = 0; j < 4; j++) acc[i][j] = pk2(0.f, 0.f);

    for (int k0 = 0; k0 < K; k0 += 16) {
        // A tile: 128x16 = 512 float4
        #pragma unroll
        for (int t = 0; t < 2; t++) {
            int idx = tid + t * 256;
            int r = idx >> 2, c4 = idx & 3;
            int gr = m0 + r;
            float4 v = make_float4(0.f, 0.f, 0.f, 0.f);
            if (gr < M) v = *(const float4*)(A + (size_t)gr * K + k0 + c4 * 4);
            As[c4 * 4 + 0][r] = v.x;
            As[c4 * 4 + 1][r] = v.y;
            As[c4 * 4 + 2][r] = v.z;
            As[c4 * 4 + 3][r] = v.w;
        }
        // B tile: 16x128 = 512 float4
        #pragma unroll
        for (int t = 0; t < 2; t++) {
            int idx = tid + t * 256;
            int r = idx >> 5, c = idx & 31;
            int gn = n0 + c * 4;
            float4 v = make_float4(0.f, 0.f, 0.f, 0.f);
            if (gn < Nn) v = *(const float4*)(W + (size_t)(k0 + r) * Nn + gn);
            *(float4*)&Bs[r][c * 4] = v;
        }
        __syncthreads();
        #pragma unroll
        for (int kk = 0; kk < 16; kk++) {
            float4 a0 = *(const float4*)&As[kk][ty * 8];
            float4 a1 = *(const float4*)&As[kk][ty * 8 + 4];
            float4 b0 = *(const float4*)&Bs[kk][tx * 8];
            float4 b1 = *(const float4*)&Bs[kk][tx * 8 + 4];
            ull bp[4] = {pk2(b0.x, b0.y), pk2(b0.z, b0.w),
                         pk2(b1.x, b1.y), pk2(b1.z, b1.w)};
            float av[8] = {a0.x, a0.y, a0.z, a0.w, a1.x, a1.y, a1.z, a1.w};
            #pragma unroll
            for (int i = 0; i < 8; i++) {
                ull ad = pk2(av[i], av[i]);
                #pragma unroll
                for (int j = 0; j < 4; j++) ffma2(acc[i][j], ad, bp[j]);
            }
        }
        __syncthreads();
    }
    #pragma unroll
    for (int i = 0; i < 8; i++) {
        int gm = m0 + ty * 8 + i;
        if (gm >= M) continue;
        float* crow = C + (size_t)gm * Nn;
        #pragma unroll
        for (int j = 0; j < 4; j++) {
            float f0, f1;
            upk2(acc[i][j], f0, f1);
            int gn0 = n0 + tx * 8 + 2 * j;
            if (gn0 < Nn) {
                float v = f0 + (BIAS ? bias[gn0] : 0.f);
                if (RELU) v = fmaxf(v, 0.f);
                crow[gn0] = v;
            }
            if (gn0 + 1 < Nn) {
                float v = f1 + (BIAS ? bias[gn0 + 1] : 0.f);
                if (RELU) v = fmaxf(v, 0.f);
                crow[gn0 + 1] = v;
            }
        }
    }
}

// ---------------- log_softmax over 40 cols, one warp per row ----------------
__global__ void lsm_kernel(const float* __restrict__ z, float* __restrict__ out) {
    int row = (blockIdx.x * blockDim.x + threadIdx.x) >> 5;
    int lane = threadIdx.x & 31;
    if (row >= NN) return;
    const float* zr = z + (size_t)row * NC;
    float v0 = (lane < NC) ? zr[lane] : -1e30f;
    float v1 = (lane + 32 < NC) ? zr[lane + 32] : -1e30f;
    float m = fmaxf(v0, v1);
    #pragma unroll
    for (int o = 16; o > 0; o >>= 1) m = fmaxf(m, __shfl_xor_sync(0xFFFFFFFFu, m, o));
    float s = ((lane < NC) ? expf(v0 - m) : 0.0f) + ((lane + 32 < NC) ? expf(v1 - m) : 0.0f);
    #pragma unroll
    for (int o = 16; o > 0; o >>= 1) s += __shfl_xor_sync(0xFFFFFFFFu, s, o);
    float lse = m + logf(s);
    float* orow = out + (size_t)row * NC;
    if (lane < NC) orow[lane] = v0 - lse;
    if (lane + 32 < NC) orow[lane + 32] = v1 - lse;
}

// ---------------- host launch ----------------
extern "C" void kernel_launch(void* const* d_in, const int* in_sizes, int n_in,
                              void* d_out, int out_size) {
    const float* x  = (const float*)d_in[0];
    const int*   ei = (const int*)d_in[1];
    const float* W1 = (const float*)d_in[2];
    const float* b1 = (const float*)d_in[3];
    const float* W2 = (const float*)d_in[4];
    const float* b2 = (const float*)d_in[5];
    const float* W3 = (const float*)d_in[6];
    const float* b3 = (const float*)d_in[7];
    const float* W4 = (const float*)d_in[8];
    const float* b4 = (const float*)d_in[9];
    float* out = (float*)d_out;

    const int* src = ei;
    const int* dst = ei + EE;

    float *deg, *inv, *ecoef, *aggx, *h, *a;
    int *cnt, *rowstart, *cursor, *eidx, *partial, *blockoff;
    cudaGetSymbolAddress((void**)&deg, g_deg);
    cudaGetSymbolAddress((void**)&inv, g_inv);
    cudaGetSymbolAddress((void**)&cnt, g_cnt);
    cudaGetSymbolAddress((void**)&rowstart, g_rowstart);
    cudaGetSymbolAddress((void**)&cursor, g_cursor);
    cudaGetSymbolAddress((void**)&eidx, g_eidx);
    cudaGetSymbolAddress((void**)&ecoef, g_ecoef);
    cudaGetSymbolAddress((void**)&aggx, g_aggx);
    cudaGetSymbolAddress((void**)&h, g_h);
    cudaGetSymbolAddress((void**)&a, g_a);
    cudaGetSymbolAddress((void**)&partial, g_partial);
    cudaGetSymbolAddress((void**)&blockoff, g_blockoff);

    const int TPB = 256;
    int gN = (NN + TPB - 1) / TPB;
    int gE = (EE + TPB - 1) / TPB;
    int gWarp1 = (NN * 32 + TPB - 1) / TPB;       // 1 warp/node
    int gWarp2 = (NN * 64 + TPB - 1) / TPB;       // 2 warps/node

    // graph preprocessing (CSR by dst)
    init_kernel<<<gN, TPB>>>(deg, cnt);
    count_kernel<<<gE, TPB>>>(dst, deg, cnt);
    inv_kernel<<<gN, TPB>>>(deg, inv);
    scan_p1<<<SCAN_NB, 256>>>(cnt, partial);
    scan_p2<<<1, 32>>>(partial, blockoff, rowstart);
    scan_p3<<<SCAN_NB, 256>>>(cnt, blockoff, rowstart, cursor);
    fill_kernel<<<gE, TPB>>>(src, dst, inv, cursor, eidx, ecoef);

    dim3 gemmGridHID(2, (NN + 127) / 128);   // 256 cols
    dim3 gemmGridC(1, (NN + 127) / 128);     // 40 cols

    // Layer 1: aggregate X at F=128, then GEMM+bias+relu
    agg_vec_kernel<FIN, 0, 0><<<gWarp1, TPB>>>(x, aggx, rowstart, eidx, ecoef, inv, nullptr);
    gemm_f2_kernel<1, 1><<<gemmGridHID, TPB>>>(aggx, W1, b1, a, NN, FIN, HID);

    // Layer 2: GEMM then aggregate+bias+relu
    gemm_f2_kernel<0, 0><<<gemmGridHID, TPB>>>(a, W2, nullptr, h, NN, HID, HID);
    agg_vec_kernel<HID, 1, 1><<<gWarp2, TPB>>>(h, a, rowstart, eidx, ecoef, inv, b2);

    // Layer 3
    gemm_f2_kernel<0, 0><<<gemmGridHID, TPB>>>(a, W3, nullptr, h, NN, HID, HID);
    agg_vec_kernel<HID, 1, 1><<<gWarp2, TPB>>>(h, a, rowstart, eidx, ecoef, inv, b3);

    // Layer 4: GEMM to 40, aggregate at F=40 (+bias), then log_softmax
    gemm_f2_kernel<0, 0><<<gemmGridC, TPB>>>(a, W4, nullptr, h, NN, HID, NC);
    agg_kernel<NC, 0, 1><<<gWarp1, TPB>>>(h, a, rowstart, eidx, ecoef, inv, b4);
    lsm_kernel<<<gWarp1, TPB>>>(a, out);
}

// round 4
// speedup vs baseline: 1.3675x; 1.3675x over previous
#include <cuda_runtime.h>
#include <cuda_bf16.h>
#include <math.h>

#define NN 50000
#define EE 1600000
#define FIN 128
#define HID 256
#define NC 40

#define SCAN_NB 100
#define SCAN_CH 500   // SCAN_NB * SCAN_CH == NN

// ---------------- scratch (device globals; no allocation) ----------------
__device__ float g_deg[NN];
__device__ float g_inv[NN];
__device__ int   g_cnt[NN];
__device__ int   g_rowstart[NN + 1];
__device__ int   g_cursor[NN];
__device__ int   g_partial[SCAN_NB];
__device__ int   g_blockoff[SCAN_NB];
__device__ int   g_eidx[EE];
__device__ float g_ecoef[EE];
__device__ float g_aggx[(size_t)NN * FIN];
__device__ float g_h[(size_t)NN * HID];
__device__ float g_a[(size_t)NN * HID];

// ---------------- graph preprocessing ----------------
__global__ void init_kernel(float* deg, int* cnt) {
    int i = blockIdx.x * blockDim.x + threadIdx.x;
    if (i < NN) { deg[i] = 1.0f; cnt[i] = 0; }   // self-loop in degree
}

__global__ void count_kernel(const int* __restrict__ dst, float* deg, int* cnt) {
    int e = blockIdx.x * blockDim.x + threadIdx.x;
    if (e < EE) {
        int d = dst[e];
        atomicAdd(&deg[d], 1.0f);
        atomicAdd(&cnt[d], 1);
    }
}

__global__ void inv_kernel(const float* __restrict__ deg, float* inv) {
    int i = blockIdx.x * blockDim.x + threadIdx.x;
    if (i < NN) inv[i] = rsqrtf(deg[i]);
}

// phase 1: per-block sums of cnt chunks
__global__ void scan_p1(const int* __restrict__ cnt, int* partial) {
    __shared__ int ws[8];
    int b = blockIdx.x, tid = threadIdx.x;
    int base = b * SCAN_CH;
    int s = 0;
    for (int i = tid; i < SCAN_CH; i += 256) s += cnt[base + i];
    #pragma unroll
    for (int o = 16; o > 0; o >>= 1) s += __shfl_xor_sync(0xFFFFFFFFu, s, o);
    if ((tid & 31) == 0) ws[tid >> 5] = s;
    __syncthreads();
    if (tid == 0) {
        int t = 0;
        #pragma unroll
        for (int j = 0; j < 8; j++) t += ws[j];
        partial[b] = t;
    }
}

// phase 2: warp-cooperative exclusive scan of the 100 partials
__global__ void scan_p2(const int* __restrict__ partial, int* blockoff, int* rowstart) {
    __shared__ int chunk_tot[4];
    int lane = threadIdx.x & 31;
    int pref[4];
    #pragma unroll
    for (int c = 0; c < 4; c++) {
        int i = c * 32 + lane;
        int v = (i < SCAN_NB) ? partial[i] : 0;
        int x = v;
        #pragma unroll
        for (int o = 1; o < 32; o <<= 1) {
            int t = __shfl_up_sync(0xFFFFFFFFu, x, o);
            if (lane >= o) x += t;
        }
        pref[c] = x - v;   // exclusive within chunk
        if (lane == 31) chunk_tot[c] = x;
    }
    __syncwarp();
    int base = 0;
    #pragma unroll
    for (int c = 0; c < 4; c++) {
        int i = c * 32 + lane;
        if (i < SCAN_NB) blockoff[i] = base + pref[c];
        base += chunk_tot[c];
    }
    if (lane == 0) rowstart[NN] = base;
}

// phase 3: per-block local exclusive scan + offset
__global__ void scan_p3(const int* __restrict__ cnt, const int* __restrict__ blockoff,
                        int* rowstart, int* cursor) {
    __shared__ int ws[8];
    __shared__ int s_run, s_tot;
    int b = blockIdx.x, tid = threadIdx.x, lane = tid & 31, w = tid >> 5;
    if (tid == 0) s_run = blockoff[b];
    __syncthreads();
    int cbase = b * SCAN_CH;
    for (int base = 0; base < SCAN_CH; base += 256) {
        int li = base + tid;
        int v = (li < SCAN_CH) ? cnt[cbase + li] : 0;
        int x = v;
        #pragma unroll
        for (int o = 1; o < 32; o <<= 1) {
            int t = __shfl_up_sync(0xFFFFFFFFu, x, o);
            if (lane >= o) x += t;
        }
        if (lane == 31) ws[w] = x;
        __syncthreads();
        if (tid == 0) {
            int s = 0;
            #pragma unroll
            for (int j = 0; j < 8; j++) { int t = ws[j]; ws[j] = s; s += t; }
            s_tot = s;
        }
        __syncthreads();
        int excl = s_run + ws[w] + x - v;
        if (li < SCAN_CH) { rowstart[cbase + li] = excl; cursor[cbase + li] = excl; }
        __syncthreads();
        if (tid == 0) s_run += s_tot;
        __syncthreads();
    }
}

__global__ void fill_kernel(const int* __restrict__ src, const int* __restrict__ dst,
                            const float* __restrict__ inv,
                            int* cursor, int* eidx, float* ecoef) {
    int e = blockIdx.x * blockDim.x + threadIdx.x;
    if (e < EE) {
        int s = src[e], d = dst[e];
        int p = atomicAdd(&cursor[d], 1);
        eidx[p] = s;
        ecoef[p] = inv[s] * inv[d];
    }
}

// ---------------- SpMM aggregation: one warp per node, register accum (R1 form) ----------------
template <int F, int RELU, int BIAS>
__global__ void agg_kernel(const float* __restrict__ hin, float* __restrict__ out,
                           const int* __restrict__ rowstart,
                           const int* __restrict__ eidx, const float* __restrict__ ecoef,
                           const float* __restrict__ inv, const float* __restrict__ bias) {
    int node = (blockIdx.x * blockDim.x + threadIdx.x) >> 5;
    int lane = threadIdx.x & 31;
    if (node >= NN) return;
    const int KC = (F + 31) / 32;
    float acc[KC];
    float sn = inv[node]; sn *= sn;
    const float* hrow = hin + (size_t)node * F;
    #pragma unroll
    for (int k = 0; k < KC; k++) {
        int c = lane + 32 * k;
        acc[k] = (c < F) ? hrow[c] * sn : 0.0f;
    }
    int beg = rowstart[node], end = rowstart[node + 1];
    for (int j = beg; j < end; j++) {
        int s = __ldg(eidx + j);
        float cf = __ldg(ecoef + j);
        const float* hs = hin + (size_t)s * F;
        #pragma unroll
        for (int k = 0; k < KC; k++) {
            int c = lane + 32 * k;
            if (c < F) acc[k] = fmaf(cf, __ldg(hs + c), acc[k]);
        }
    }
    float* orow = out + (size_t)node * F;
    #pragma unroll
    for (int k = 0; k < KC; k++) {
        int c = lane + 32 * k;
        if (c < F) {
            float v = acc[k] + (BIAS ? bias[c] : 0.0f);
            if (RELU) v = fmaxf(v, 0.0f);
            orow[c] = v;
        }
    }
}

// ---------------- tf32 tensor-core GEMM ----------------
// C[M,Nn] = A[M,K] @ W[K,Nn] (+bias)(+relu); K multiple of 32.
// BM=128, BN=128, BK=32, 256 threads (8 warps as 4m x 2n), warp tile 32m x 64n.
__device__ __forceinline__ unsigned tf32_bits(float x) {
    unsigned u;
    asm("cvt.rna.tf32.f32 %0, %1;" : "=r"(u) : "f"(x));
    return u;
}

template <int RELU, int BIAS>
__global__ void __launch_bounds__(256)
gemm_tc_kernel(const float* __restrict__ A, const float* __restrict__ W,
               const float* __restrict__ bias, float* __restrict__ C,
               int M, int K, int Nn) {
    __shared__ float As[32][132];   // [k][m], tf32-rounded bits
    __shared__ float Bs[32][132];   // [k][n], tf32-rounded bits
    int tid = threadIdx.x;
    int wid = tid >> 5, lane = tid & 31;
    int gid = lane >> 2, tig = lane & 3;     // groupID, threadID_in_group
    int m0 = blockIdx.y * 128;
    int n0 = blockIdx.x * 128;
    int mbase = (wid >> 1) * 32;             // warp m offset in tile
    int nbase = (wid & 1) * 64;              // warp n offset in tile

    float acc[2][8][4];
    #pragma unroll
    for (int mt = 0; mt < 2; mt++)
        #pragma unroll
        for (int nt = 0; nt < 8; nt++)
            #pragma unroll
            for (int q = 0; q < 4; q++) acc[mt][nt][q] = 0.0f;

    for (int k0 = 0; k0 < K; k0 += 32) {
        // stage A tile [128m x 32k] -> As[k][m] with tf32 rounding
        #pragma unroll
        for (int t = 0; t < 4; t++) {
            int idx = tid + t * 256;          // 1024 float4
            int r = idx >> 3, c4 = idx & 7;   // row 0..127, k-quad 0..7
            int gr = m0 + r;
            float4 v = make_float4(0.f, 0.f, 0.f, 0.f);
            if (gr < M) v = *(const float4*)(A + (size_t)gr * K + k0 + c4 * 4);
            As[c4 * 4 + 0][r] = __uint_as_float(tf32_bits(v.x));
            As[c4 * 4 + 1][r] = __uint_as_float(tf32_bits(v.y));
            As[c4 * 4 + 2][r] = __uint_as_float(tf32_bits(v.z));
            As[c4 * 4 + 3][r] = __uint_as_float(tf32_bits(v.w));
        }
        // stage B tile [32k x 128n] -> Bs[k][n] with tf32 rounding
        #pragma unroll
        for (int t = 0; t < 4; t++) {
            int idx = tid + t * 256;
            int r = idx >> 5, c = idx & 31;   // k row, n quad
            int gn = n0 + c * 4;
            float4 v = make_float4(0.f, 0.f, 0.f, 0.f);
            if (gn + 3 < Nn) {
                v = *(const float4*)(W + (size_t)(k0 + r) * Nn + gn);
            } else if (gn < Nn) {
                const float* wr = W + (size_t)(k0 + r) * Nn;
                v.x = wr[gn];
                if (gn + 1 < Nn) v.y = wr[gn + 1];
                if (gn + 2 < Nn) v.z = wr[gn + 2];
            }
            Bs[r][c * 4 + 0] = __uint_as_float(tf32_bits(v.x));
            Bs[r][c * 4 + 1] = __uint_as_float(tf32_bits(v.y));
            Bs[r][c * 4 + 2] = __uint_as_float(tf32_bits(v.z));
            Bs[r][c * 4 + 3] = __uint_as_float(tf32_bits(v.w));
        }
        __syncthreads();

        #pragma unroll
        for (int kk = 0; kk < 4; kk++) {
            int kf = kk * 8;
            unsigned af[2][4], bf[8][2];
            #pragma unroll
            for (int mt = 0; mt < 2; mt++) {
                int mr = mbase + mt * 16 + gid;
                af[mt][0] = __float_as_uint(As[kf + tig][mr]);
                af[mt][1] = __float_as_uint(As[kf + tig][mr + 8]);
                af[mt][2] = __float_as_uint(As[kf + tig + 4][mr]);
                af[mt][3] = __float_as_uint(As[kf + tig + 4][mr + 8]);
            }
            #pragma unroll
            for (int nt = 0; nt < 8; nt++) {
                int nc = nbase + nt * 8 + gid;
                bf[nt][0] = __float_as_uint(Bs[kf + tig][nc]);
                bf[nt][1] = __float_as_uint(Bs[kf + tig + 4][nc]);
            }
            #pragma unroll
            for (int mt = 0; mt < 2; mt++)
                #pragma unroll
                for (int nt = 0; nt < 8; nt++) {
                    asm volatile(
                        "mma.sync.aligned.m16n8k8.row.col.f32.tf32.tf32.f32 "
                        "{%0,%1,%2,%3},{%4,%5,%6,%7},{%8,%9},{%0,%1,%2,%3};"
                        : "+f"(acc[mt][nt][0]), "+f"(acc[mt][nt][1]),
                          "+f"(acc[mt][nt][2]), "+f"(acc[mt][nt][3])
                        : "r"(af[mt][0]), "r"(af[mt][1]), "r"(af[mt][2]), "r"(af[mt][3]),
                          "r"(bf[nt][0]), "r"(bf[nt][1]));
                }
        }
        __syncthreads();
    }

    // epilogue
    #pragma unroll
    for (int mt = 0; mt < 2; mt++) {
        int row0 = m0 + mbase + mt * 16 + gid;
        #pragma unroll
        for (int nt = 0; nt < 8; nt++) {
            int col0 = n0 + nbase + nt * 8 + tig * 2;
            #pragma unroll
            for (int h = 0; h < 2; h++) {   // h=0: rows row0; h=1: row0+8
                int r = row0 + h * 8;
                if (r >= M) continue;
                float v0 = acc[mt][nt][h * 2 + 0];
                float v1 = acc[mt][nt][h * 2 + 1];
                if (col0 < Nn) {
                    float v = v0 + (BIAS ? bias[col0] : 0.f);
                    if (RELU) v = fmaxf(v, 0.f);
                    C[(size_t)r * Nn + col0] = v;
                }
                if (col0 + 1 < Nn) {
                    float v = v1 + (BIAS ? bias[col0 + 1] : 0.f);
                    if (RELU) v = fmaxf(v, 0.f);
                    C[(size_t)r * Nn + col0 + 1] = v;
                }
            }
        }
    }
}

// ---------------- log_softmax over 40 cols, one warp per row ----------------
__global__ void lsm_kernel(const float* __restrict__ z, float* __restrict__ out) {
    int row = (blockIdx.x * blockDim.x + threadIdx.x) >> 5;
    int lane = threadIdx.x & 31;
    if (row >= NN) return;
    const float* zr = z + (size_t)row * NC;
    float v0 = (lane < NC) ? zr[lane] : -1e30f;
    float v1 = (lane + 32 < NC) ? zr[lane + 32] : -1e30f;
    float m = fmaxf(v0, v1);
    #pragma unroll
    for (int o = 16; o > 0; o >>= 1) m = fmaxf(m, __shfl_xor_sync(0xFFFFFFFFu, m, o));
    float s = ((lane < NC) ? expf(v0 - m) : 0.0f) + ((lane + 32 < NC) ? expf(v1 - m) : 0.0f);
    #pragma unroll
    for (int o = 16; o > 0; o >>= 1) s += __shfl_xor_sync(0xFFFFFFFFu, s, o);
    float lse = m + logf(s);
    float* orow = out + (size_t)row * NC;
    if (lane < NC) orow[lane] = v0 - lse;
    if (lane + 32 < NC) orow[lane + 32] = v1 - lse;
}

// ---------------- host launch ----------------
extern "C" void kernel_launch(void* const* d_in, const int* in_sizes, int n_in,
                              void* d_out, int out_size) {
    const float* x  = (const float*)d_in[0];
    const int*   ei = (const int*)d_in[1];
    const float* W1 = (const float*)d_in[2];
    const float* b1 = (const float*)d_in[3];
    const float* W2 = (const float*)d_in[4];
    const float* b2 = (const float*)d_in[5];
    const float* W3 = (const float*)d_in[6];
    const float* b3 = (const float*)d_in[7];
    const float* W4 = (const float*)d_in[8];
    const float* b4 = (const float*)d_in[9];
    float* out = (float*)d_out;

    const int* src = ei;
    const int* dst = ei + EE;

    float *deg, *inv, *ecoef, *aggx, *h, *a;
    int *cnt, *rowstart, *cursor, *eidx, *partial, *blockoff;
    cudaGetSymbolAddress((void**)&deg, g_deg);
    cudaGetSymbolAddress((void**)&inv, g_inv);
    cudaGetSymbolAddress((void**)&cnt, g_cnt);
    cudaGetSymbolAddress((void**)&rowstart, g_rowstart);
    cudaGetSymbolAddress((void**)&cursor, g_cursor);
    cudaGetSymbolAddress((void**)&eidx, g_eidx);
    cudaGetSymbolAddress((void**)&ecoef, g_ecoef);
    cudaGetSymbolAddress((void**)&aggx, g_aggx);
    cudaGetSymbolAddress((void**)&h, g_h);
    cudaGetSymbolAddress((void**)&a, g_a);
    cudaGetSymbolAddress((void**)&partial, g_partial);
    cudaGetSymbolAddress((void**)&blockoff, g_blockoff);

    const int TPB = 256;
    int gN = (NN + TPB - 1) / TPB;
    int gE = (EE + TPB - 1) / TPB;
    int gWarp1 = (NN * 32 + TPB - 1) / TPB;   // 1 warp/node

    // graph preprocessing (CSR by dst)
    init_kernel<<<gN, TPB>>>(deg, cnt);
    count_kernel<<<gE, TPB>>>(dst, deg, cnt);
    inv_kernel<<<gN, TPB>>>(deg, inv);
    scan_p1<<<SCAN_NB, 256>>>(cnt, partial);
    scan_p2<<<1, 32>>>(partial, blockoff, rowstart);
    scan_p3<<<SCAN_NB, 256>>>(cnt, blockoff, rowstart, cursor);
    fill_kernel<<<gE, TPB>>>(src, dst, inv, cursor, eidx, ecoef);

    dim3 gridHID(2, (NN + 127) / 128);   // N=256
    dim3 gridC(1, (NN + 127) / 128);     // N=40

    // Layer 1: aggregate X at F=128 first, then GEMM+bias+relu
    agg_kernel<FIN, 0, 0><<<gWarp1, TPB>>>(x, aggx, rowstart, eidx, ecoef, inv, nullptr);
    gemm_tc_kernel<1, 1><<<gridHID, TPB>>>(aggx, W1, b1, a, NN, FIN, HID);

    // Layer 2: GEMM then aggregate+bias+relu
    gemm_tc_kernel<0, 0><<<gridHID, TPB>>>(a, W2, nullptr, h, NN, HID, HID);
    agg_kernel<HID, 1, 1><<<gWarp1, TPB>>>(h, a, rowstart, eidx, ecoef, inv, b2);

    // Layer 3
    gemm_tc_kernel<0, 0><<<gridHID, TPB>>>(a, W3, nullptr, h, NN, HID, HID);
    agg_kernel<HID, 1, 1><<<gWarp1, TPB>>>(h, a, rowstart, eidx, ecoef, inv, b3);

    // Layer 4: GEMM to 40, aggregate at F=40 (+bias), then log_softmax
    gemm_tc_kernel<0, 0><<<gridC, TPB>>>(a, W4, nullptr, h, NN, HID, NC);
    agg_kernel<NC, 0, 1><<<gWarp1, TPB>>>(h, a, rowstart, eidx, ecoef, inv, b4);
    lsm_kernel<<<gWarp1, TPB>>>(a, out);
}

// round 8
// speedup vs baseline: 1.5451x; 1.1299x over previous
#include <cuda_runtime.h>
#include <cuda_bf16.h>
#include <math.h>

#define NN 50000
#define EE 1600000
#define FIN 128
#define HID 256
#define NC 40

#define SCAN_NB 100
#define SCAN_CH 500   // SCAN_NB * SCAN_CH == NN

// ---------------- scratch (device globals; no allocation) ----------------
__device__ float g_inv[NN];
__device__ int   g_cnt[NN];
__device__ int   g_rowstart[NN + 1];
__device__ int   g_cursor[NN];
__device__ int   g_partial[SCAN_NB];
__device__ int   g_blockoff[SCAN_NB];
__device__ int   g_eidx[EE];
__device__ float g_ecoef[EE];
__device__ __nv_bfloat16 g_xb[(size_t)NN * FIN];   // bf16 copy of x
__device__ __nv_bfloat16 g_hb[(size_t)NN * HID];   // bf16 pre-agg hidden
__device__ float g_aggx[(size_t)NN * FIN];
__device__ float g_h[(size_t)NN * HID];            // fp32 scratch (layer-4 logits etc.)
__device__ float g_a[(size_t)NN * HID];

// ---------------- graph preprocessing ----------------
__global__ void init_kernel(int* cnt) {
    int i = blockIdx.x * blockDim.x + threadIdx.x;
    if (i < NN) cnt[i] = 0;
}

__global__ void count_kernel(const int* __restrict__ dst, int* cnt) {
    int e = blockIdx.x * blockDim.x + threadIdx.x;
    if (e < EE) atomicAdd(&cnt[dst[e]], 1);
}

__global__ void inv_kernel(const int* __restrict__ cnt, float* inv) {
    int i = blockIdx.x * blockDim.x + threadIdx.x;
    if (i < NN) inv[i] = rsqrtf((float)cnt[i] + 1.0f);   // +1 self-loop
}

// phase 1: per-block sums of cnt chunks
__global__ void scan_p1(const int* __restrict__ cnt, int* partial) {
    __shared__ int ws[8];
    int b = blockIdx.x, tid = threadIdx.x;
    int base = b * SCAN_CH;
    int s = 0;
    for (int i = tid; i < SCAN_CH; i += 256) s += cnt[base + i];
    #pragma unroll
    for (int o = 16; o > 0; o >>= 1) s += __shfl_xor_sync(0xFFFFFFFFu, s, o);
    if ((tid & 31) == 0) ws[tid >> 5] = s;
    __syncthreads();
    if (tid == 0) {
        int t = 0;
        #pragma unroll
        for (int j = 0; j < 8; j++) t += ws[j];
        partial[b] = t;
    }
}

// phase 2: warp-cooperative exclusive scan of the 100 partials
__global__ void scan_p2(const int* __restrict__ partial, int* blockoff, int* rowstart) {
    __shared__ int chunk_tot[4];
    int lane = threadIdx.x & 31;
    int pref[4];
    #pragma unroll
    for (int c = 0; c < 4; c++) {
        int i = c * 32 + lane;
        int v = (i < SCAN_NB) ? partial[i] : 0;
        int x = v;
        #pragma unroll
        for (int o = 1; o < 32; o <<= 1) {
            int t = __shfl_up_sync(0xFFFFFFFFu, x, o);
            if (lane >= o) x += t;
        }
        pref[c] = x - v;
        if (lane == 31) chunk_tot[c] = x;
    }
    __syncwarp();
    int base = 0;
    #pragma unroll
    for (int c = 0; c < 4; c++) {
        int i = c * 32 + lane;
        if (i < SCAN_NB) blockoff[i] = base + pref[c];
        base += chunk_tot[c];
    }
    if (lane == 0) rowstart[NN] = base;
}

// phase 3: per-block local exclusive scan + offset
__global__ void scan_p3(const int* __restrict__ cnt, const int* __restrict__ blockoff,
                        int* rowstart, int* cursor) {
    __shared__ int ws[8];
    __shared__ int s_run, s_tot;
    int b = blockIdx.x, tid = threadIdx.x, lane = tid & 31, w = tid >> 5;
    if (tid == 0) s_run = blockoff[b];
    __syncthreads();
    int cbase = b * SCAN_CH;
    for (int base = 0; base < SCAN_CH; base += 256) {
        int li = base + tid;
        int v = (li < SCAN_CH) ? cnt[cbase + li] : 0;
        int x = v;
        #pragma unroll
        for (int o = 1; o < 32; o <<= 1) {
            int t = __shfl_up_sync(0xFFFFFFFFu, x, o);
            if (lane >= o) x += t;
        }
        if (lane == 31) ws[w] = x;
        __syncthreads();
        if (tid == 0) {
            int s = 0;
            #pragma unroll
            for (int j = 0; j < 8; j++) { int t = ws[j]; ws[j] = s; s += t; }
            s_tot = s;
        }
        __syncthreads();
        int excl = s_run + ws[w] + x - v;
        if (li < SCAN_CH) { rowstart[cbase + li] = excl; cursor[cbase + li] = excl; }
        __syncthreads();
        if (tid == 0) s_run += s_tot;
        __syncthreads();
    }
}

__global__ void fill_kernel(const int* __restrict__ src, const int* __restrict__ dst,
                            const float* __restrict__ inv,
                            int* cursor, int* eidx, float* ecoef) {
    int e = blockIdx.x * blockDim.x + threadIdx.x;
    if (e < EE) {
        int s = src[e], d = dst[e];
        int p = atomicAdd(&cursor[d], 1);
        eidx[p] = s;
        ecoef[p] = inv[s] * inv[d];
    }
}

// ---------------- fp32 -> bf16 convert ----------------
__global__ void cvt_bf16_kernel(const float* __restrict__ in, __nv_bfloat16* __restrict__ out,
                                int n4) {
    int i = blockIdx.x * blockDim.x + threadIdx.x;
    if (i < n4) {
        float4 v = *(const float4*)(in + (size_t)i * 4);
        __nv_bfloat162 p0 = __floats2bfloat162_rn(v.x, v.y);
        __nv_bfloat162 p1 = __floats2bfloat162_rn(v.z, v.w);
        *(__nv_bfloat162*)(out + (size_t)i * 4) = p0;
        *(__nv_bfloat162*)(out + (size_t)i * 4 + 2) = p1;
    }
}

// ---------------- bf16-gather SpMM aggregation: one warp per node ----------------
// Gathers bf16 rows, accumulates fp32, writes fp32 (+bias)(+relu).
// F multiple of 64. Lane handles column pairs {lane*2 + 64k, +1}.
template <int F, int RELU, int BIAS>
__global__ void agg_bf16_kernel(const __nv_bfloat16* __restrict__ hin, float* __restrict__ out,
                                const int* __restrict__ rowstart,
                                const int* __restrict__ eidx, const float* __restrict__ ecoef,
                                const float* __restrict__ inv, const float* __restrict__ bias) {
    int node = (blockIdx.x * blockDim.x + threadIdx.x) >> 5;
    int lane = threadIdx.x & 31;
    if (node >= NN) return;
    const int KC = F / 64;
    float2 acc[KC];
    float sn = inv[node]; sn *= sn;
    const __nv_bfloat16* hrow = hin + (size_t)node * F;
    #pragma unroll
    for (int k = 0; k < KC; k++) {
        float2 v = __bfloat1622float2(*(const __nv_bfloat162*)(hrow + lane * 2 + 64 * k));
        acc[k].x = v.x * sn;
        acc[k].y = v.y * sn;
    }
    int beg = rowstart[node], end = rowstart[node + 1];
    for (int j = beg; j < end; j++) {
        int s = __ldg(eidx + j);
        float cf = __ldg(ecoef + j);
        const __nv_bfloat16* hs = hin + (size_t)s * F;
        #pragma unroll
        for (int k = 0; k < KC; k++) {
            float2 v = __bfloat1622float2(
                *(const __nv_bfloat162*)(hs + lane * 2 + 64 * k));
            acc[k].x = fmaf(cf, v.x, acc[k].x);
            acc[k].y = fmaf(cf, v.y, acc[k].y);
        }
    }
    float* orow = out + (size_t)node * F;
    #pragma unroll
    for (int k = 0; k < KC; k++) {
        int c = lane * 2 + 64 * k;
        float vx = acc[k].x + (BIAS ? bias[c] : 0.0f);
        float vy = acc[k].y + (BIAS ? bias[c + 1] : 0.0f);
        if (RELU) { vx = fmaxf(vx, 0.0f); vy = fmaxf(vy, 0.0f); }
        *(float2*)(orow + c) = make_float2(vx, vy);
    }
}

// fp32 scalar agg (layer 4, F=40; protects output precision)
template <int F, int RELU, int BIAS>
__global__ void agg_kernel(const float* __restrict__ hin, float* __restrict__ out,
                           const int* __restrict__ rowstart,
                           const int* __restrict__ eidx, const float* __restrict__ ecoef,
                           const float* __restrict__ inv, const float* __restrict__ bias) {
    int node = (blockIdx.x * blockDim.x + threadIdx.x) >> 5;
    int lane = threadIdx.x & 31;
    if (node >= NN) return;
    const int KC = (F + 31) / 32;
    float acc[KC];
    float sn = inv[node]; sn *= sn;
    const float* hrow = hin + (size_t)node * F;
    #pragma unroll
    for (int k = 0; k < KC; k++) {
        int c = lane + 32 * k;
        acc[k] = (c < F) ? hrow[c] * sn : 0.0f;
    }
    int beg = rowstart[node], end = rowstart[node + 1];
    for (int j = beg; j < end; j++) {
        int s = __ldg(eidx + j);
        float cf = __ldg(ecoef + j);
        const float* hs = hin + (size_t)s * F;
        #pragma unroll
        for (int k = 0; k < KC; k++) {
            int c = lane + 32 * k;
            if (c < F) acc[k] = fmaf(cf, __ldg(hs + c), acc[k]);
        }
    }
    float* orow = out + (size_t)node * F;
    #pragma unroll
    for (int k = 0; k < KC; k++) {
        int c = lane + 32 * k;
        if (c < F) {
            float v = acc[k] + (BIAS ? bias[c] : 0.0f);
            if (RELU) v = fmaxf(v, 0.0f);
            orow[c] = v;
        }
    }
}

// ---------------- tf32 tensor-core GEMM ----------------
// C[M,Nn] = A[M,K] @ W[K,Nn] (+bias)(+relu); K multiple of 32.
// BM=128, BN=128, BK=32, 256 threads (8 warps as 4m x 2n), warp tile 32m x 64n.
// BF16OUT: store as bf16 instead of fp32.
__device__ __forceinline__ unsigned tf32_bits(float x) {
    unsigned u;
    asm("cvt.rna.tf32.f32 %0, %1;" : "=r"(u) : "f"(x));
    return u;
}

template <int RELU, int BIAS, int BF16OUT>
__global__ void __launch_bounds__(256)
gemm_tc_kernel(const float* __restrict__ A, const float* __restrict__ W,
               const float* __restrict__ bias, void* __restrict__ Cv,
               int M, int K, int Nn) {
    __shared__ float As[32][132];   // [k][m]
    __shared__ float Bs[32][132];   // [k][n]
    int tid = threadIdx.x;
    int wid = tid >> 5, lane = tid & 31;
    int gid = lane >> 2, tig = lane & 3;
    int m0 = blockIdx.y * 128;
    int n0 = blockIdx.x * 128;
    int mbase = (wid >> 1) * 32;
    int nbase = (wid & 1) * 64;

    float acc[2][8][4];
    #pragma unroll
    for (int mt = 0; mt < 2; mt++)
        #pragma unroll
        for (int nt = 0; nt < 8; nt++)
            #pragma unroll
            for (int q = 0; q < 4; q++) acc[mt][nt][q] = 0.0f;

    for (int k0 = 0; k0 < K; k0 += 32) {
        #pragma unroll
        for (int t = 0; t < 4; t++) {
            int idx = tid + t * 256;
            int r = idx >> 3, c4 = idx & 7;
            int gr = m0 + r;
            float4 v = make_float4(0.f, 0.f, 0.f, 0.f);
            if (gr < M) v = *(const float4*)(A + (size_t)gr * K + k0 + c4 * 4);
            As[c4 * 4 + 0][r] = __uint_as_float(tf32_bits(v.x));
            As[c4 * 4 + 1][r] = __uint_as_float(tf32_bits(v.y));
            As[c4 * 4 + 2][r] = __uint_as_float(tf32_bits(v.z));
            As[c4 * 4 + 3][r] = __uint_as_float(tf32_bits(v.w));
        }
        #pragma unroll
        for (int t = 0; t < 4; t++) {
            int idx = tid + t * 256;
            int r = idx >> 5, c = idx & 31;
            int gn = n0 + c * 4;
            float4 v = make_float4(0.f, 0.f, 0.f, 0.f);
            if (gn + 3 < Nn) {
                v = *(const float4*)(W + (size_t)(k0 + r) * Nn + gn);
            } else if (gn < Nn) {
                const float* wr = W + (size_t)(k0 + r) * Nn;
                v.x = wr[gn];
                if (gn + 1 < Nn) v.y = wr[gn + 1];
                if (gn + 2 < Nn) v.z = wr[gn + 2];
            }
            Bs[r][c * 4 + 0] = __uint_as_float(tf32_bits(v.x));
            Bs[r][c * 4 + 1] = __uint_as_float(tf32_bits(v.y));
            Bs[r][c * 4 + 2] = __uint_as_float(tf32_bits(v.z));
            Bs[r][c * 4 + 3] = __uint_as_float(tf32_bits(v.w));
        }
        __syncthreads();

        #pragma unroll
        for (int kk = 0; kk < 4; kk++) {
            int kf = kk * 8;
            unsigned af[2][4], bf[8][2];
            #pragma unroll
            for (int mt = 0; mt < 2; mt++) {
                int mr = mbase + mt * 16 + gid;
                af[mt][0] = __float_as_uint(As[kf + tig][mr]);
                af[mt][1] = __float_as_uint(As[kf + tig][mr + 8]);
                af[mt][2] = __float_as_uint(As[kf + tig + 4][mr]);
                af[mt][3] = __float_as_uint(As[kf + tig + 4][mr + 8]);
            }
            #pragma unroll
            for (int nt = 0; nt < 8; nt++) {
                int nc = nbase + nt * 8 + gid;
                bf[nt][0] = __float_as_uint(Bs[kf + tig][nc]);
                bf[nt][1] = __float_as_uint(Bs[kf + tig + 4][nc]);
            }
            #pragma unroll
            for (int mt = 0; mt < 2; mt++)
                #pragma unroll
                for (int nt = 0; nt < 8; nt++) {
                    asm volatile(
                        "mma.sync.aligned.m16n8k8.row.col.f32.tf32.tf32.f32 "
                        "{%0,%1,%2,%3},{%4,%5,%6,%7},{%8,%9},{%0,%1,%2,%3};"
                        : "+f"(acc[mt][nt][0]), "+f"(acc[mt][nt][1]),
                          "+f"(acc[mt][nt][2]), "+f"(acc[mt][nt][3])
                        : "r"(af[mt][0]), "r"(af[mt][1]), "r"(af[mt][2]), "r"(af[mt][3]),
                          "r"(bf[nt][0]), "r"(bf[nt][1]));
                }
        }
        __syncthreads();
    }

    // epilogue
    #pragma unroll
    for (int mt = 0; mt < 2; mt++) {
        int row0 = m0 + mbase + mt * 16 + gid;
        #pragma unroll
        for (int nt = 0; nt < 8; nt++) {
            int col0 = n0 + nbase + nt * 8 + tig * 2;
            #pragma unroll
            for (int h = 0; h < 2; h++) {
                int r = row0 + h * 8;
                if (r >= M) continue;
                float v0 = acc[mt][nt][h * 2 + 0] + (BIAS ? bias[col0] : 0.f);
                float v1 = acc[mt][nt][h * 2 + 1] +
                           (BIAS ? ((col0 + 1 < Nn) ? bias[col0 + 1] : 0.f) : 0.f);
                if (RELU) { v0 = fmaxf(v0, 0.f); v1 = fmaxf(v1, 0.f); }
                if (BF16OUT) {
                    __nv_bfloat16* Cb = (__nv_bfloat16*)Cv;
                    if (col0 + 1 < Nn) {
                        *(__nv_bfloat162*)(Cb + (size_t)r * Nn + col0) =
                            __floats2bfloat162_rn(v0, v1);
                    } else if (col0 < Nn) {
                        Cb[(size_t)r * Nn + col0] = __float2bfloat16(v0);
                    }
                } else {
                    float* Cf = (float*)Cv;
                    if (col0 < Nn) Cf[(size_t)r * Nn + col0] = v0;
                    if (col0 + 1 < Nn) Cf[(size_t)r * Nn + col0 + 1] = v1;
                }
            }
        }
    }
}

// ---------------- log_softmax over 40 cols, one warp per row ----------------
__global__ void lsm_kernel(const float* __restrict__ z, float* __restrict__ out) {
    int row = (blockIdx.x * blockDim.x + threadIdx.x) >> 5;
    int lane = threadIdx.x & 31;
    if (row >= NN) return;
    const float* zr = z + (size_t)row * NC;
    float v0 = (lane < NC) ? zr[lane] : -1e30f;
    float v1 = (lane + 32 < NC) ? zr[lane + 32] : -1e30f;
    float m = fmaxf(v0, v1);
    #pragma unroll
    for (int o = 16; o > 0; o >>= 1) m = fmaxf(m, __shfl_xor_sync(0xFFFFFFFFu, m, o));
    float s = ((lane < NC) ? expf(v0 - m) : 0.0f) + ((lane + 32 < NC) ? expf(v1 - m) : 0.0f);
    #pragma unroll
    for (int o = 16; o > 0; o >>= 1) s += __shfl_xor_sync(0xFFFFFFFFu, s, o);
    float lse = m + logf(s);
    float* orow = out + (size_t)row * NC;
    if (lane < NC) orow[lane] = v0 - lse;
    if (lane + 32 < NC) orow[lane + 32] = v1 - lse;
}

// ---------------- host launch ----------------
extern "C" void kernel_launch(void* const* d_in, const int* in_sizes, int n_in,
                              void* d_out, int out_size) {
    const float* x  = (const float*)d_in[0];
    const int*   ei = (const int*)d_in[1];
    const float* W1 = (const float*)d_in[2];
    const float* b1 = (const float*)d_in[3];
    const float* W2 = (const float*)d_in[4];
    const float* b2 = (const float*)d_in[5];
    const float* W3 = (const float*)d_in[6];
    const float* b3 = (const float*)d_in[7];
    const float* W4 = (const float*)d_in[8];
    const float* b4 = (const float*)d_in[9];
    float* out = (float*)d_out;

    const int* src = ei;
    const int* dst = ei + EE;

    float *inv, *ecoef, *aggx, *h, *a;
    int *cnt, *rowstart, *cursor, *eidx, *partial, *blockoff;
    __nv_bfloat16 *xb, *hb;
    cudaGetSymbolAddress((void**)&inv, g_inv);
    cudaGetSymbolAddress((void**)&cnt, g_cnt);
    cudaGetSymbolAddress((void**)&rowstart, g_rowstart);
    cudaGetSymbolAddress((void**)&cursor, g_cursor);
    cudaGetSymbolAddress((void**)&eidx, g_eidx);
    cudaGetSymbolAddress((void**)&ecoef, g_ecoef);
    cudaGetSymbolAddress((void**)&aggx, g_aggx);
    cudaGetSymbolAddress((void**)&h, g_h);
    cudaGetSymbolAddress((void**)&a, g_a);
    cudaGetSymbolAddress((void**)&partial, g_partial);
    cudaGetSymbolAddress((void**)&blockoff, g_blockoff);
    cudaGetSymbolAddress((void**)&xb, g_xb);
    cudaGetSymbolAddress((void**)&hb, g_hb);

    const int TPB = 256;
    int gN = (NN + TPB - 1) / TPB;
    int gE = (EE + TPB - 1) / TPB;
    int gWarp1 = (NN * 32 + TPB - 1) / TPB;   // 1 warp/node
    int nX4 = NN * FIN / 4;
    int gX4 = (nX4 + TPB - 1) / TPB;

    // graph preprocessing (CSR by dst)
    init_kernel<<<gN, TPB>>>(cnt);
    count_kernel<<<gE, TPB>>>(dst, cnt);
    inv_kernel<<<gN, TPB>>>(cnt, inv);
    scan_p1<<<SCAN_NB, 256>>>(cnt, partial);
    scan_p2<<<1, 32>>>(partial, blockoff, rowstart);
    scan_p3<<<SCAN_NB, 256>>>(cnt, blockoff, rowstart, cursor);
    fill_kernel<<<gE, TPB>>>(src, dst, inv, cursor, eidx, ecoef);

    // x -> bf16
    cvt_bf16_kernel<<<gX4, TPB>>>(x, xb, nX4);

    dim3 gridHID(2, (NN + 127) / 128);   // N=256
    dim3 gridC(1, (NN + 127) / 128);     // N=40

    // Layer 1: aggregate bf16 x at F=128, then GEMM(+bias+relu) -> fp32 a
    agg_bf16_kernel<FIN, 0, 0><<<gWarp1, TPB>>>(xb, aggx, rowstart, eidx, ecoef, inv, nullptr);
    gemm_tc_kernel<1, 1, 0><<<gridHID, TPB>>>(aggx, W1, b1, a, NN, FIN, HID);

    // Layer 2: GEMM -> bf16 h, aggregate bf16 (+bias+relu) -> fp32 a
    gemm_tc_kernel<0, 0, 1><<<gridHID, TPB>>>(a, W2, nullptr, hb, NN, HID, HID);
    agg_bf16_kernel<HID, 1, 1><<<gWarp1, TPB>>>(hb, a, rowstart, eidx, ecoef, inv, b2);

    // Layer 3
    gemm_tc_kernel<0, 0, 1><<<gridHID, TPB>>>(a, W3, nullptr, hb, NN, HID, HID);
    agg_bf16_kernel<HID, 1, 1><<<gWarp1, TPB>>>(hb, a, rowstart, eidx, ecoef, inv, b3);

    // Layer 4: fp32 all the way (logits feed log_softmax)
    gemm_tc_kernel<0, 0, 0><<<gridC, TPB>>>(a, W4, nullptr, h, NN, HID, NC);
    agg_kernel<NC, 0, 1><<<gWarp1, TPB>>>(h, a, rowstart, eidx, ecoef, inv, b4);
    lsm_kernel<<<gWarp1, TPB>>>(a, out);
}

// round 9
// speedup vs baseline: 1.5907x; 1.0295x over previous
#include <cuda_runtime.h>
#include <cuda_bf16.h>
#include <math.h>

#define NN 50000
#define EE 1600000
#define FIN 128
#define HID 256
#define NC 40

#define SCAN_NB 100
#define SCAN_CH 500   // SCAN_NB * SCAN_CH == NN

// ---------------- scratch (device globals; no allocation) ----------------
__device__ float g_inv[NN];
__device__ int   g_cnt[NN];
__device__ int   g_rowstart[NN + 1];
__device__ int   g_cursor[NN];
__device__ int   g_partial[SCAN_NB];
__device__ int   g_blockoff[SCAN_NB];
__device__ int2  g_edge[EE];                        // {src, coef bits}
__device__ __nv_bfloat16 g_xb [(size_t)NN * FIN];   // bf16 x
__device__ __nv_bfloat16 g_axb[(size_t)NN * FIN];   // bf16 agg(x)
__device__ __nv_bfloat16 g_p  [(size_t)NN * HID];   // bf16 ping
__device__ __nv_bfloat16 g_q  [(size_t)NN * HID];   // bf16 pong
__device__ float g_h[(size_t)NN * 64];              // fp32 layer-4 logits
__device__ float g_a[(size_t)NN * 64];              // fp32 layer-4 agg out

// ---------------- graph preprocessing ----------------
__global__ void init_kernel(int* cnt) {
    int i = blockIdx.x * blockDim.x + threadIdx.x;
    if (i < NN) cnt[i] = 0;
}

__global__ void count_kernel(const int* __restrict__ dst, int* cnt) {
    int e = blockIdx.x * blockDim.x + threadIdx.x;
    if (e < EE) atomicAdd(&cnt[dst[e]], 1);
}

__global__ void inv_kernel(const int* __restrict__ cnt, float* inv) {
    int i = blockIdx.x * blockDim.x + threadIdx.x;
    if (i < NN) inv[i] = rsqrtf((float)cnt[i] + 1.0f);   // +1 self-loop
}

__global__ void scan_p1(const int* __restrict__ cnt, int* partial) {
    __shared__ int ws[8];
    int b = blockIdx.x, tid = threadIdx.x;
    int base = b * SCAN_CH;
    int s = 0;
    for (int i = tid; i < SCAN_CH; i += 256) s += cnt[base + i];
    #pragma unroll
    for (int o = 16; o > 0; o >>= 1) s += __shfl_xor_sync(0xFFFFFFFFu, s, o);
    if ((tid & 31) == 0) ws[tid >> 5] = s;
    __syncthreads();
    if (tid == 0) {
        int t = 0;
        #pragma unroll
        for (int j = 0; j < 8; j++) t += ws[j];
        partial[b] = t;
    }
}

__global__ void scan_p2(const int* __restrict__ partial, int* blockoff, int* rowstart) {
    __shared__ int chunk_tot[4];
    int lane = threadIdx.x & 31;
    int pref[4];
    #pragma unroll
    for (int c = 0; c < 4; c++) {
        int i = c * 32 + lane;
        int v = (i < SCAN_NB) ? partial[i] : 0;
        int x = v;
        #pragma unroll
        for (int o = 1; o < 32; o <<= 1) {
            int t = __shfl_up_sync(0xFFFFFFFFu, x, o);
            if (lane >= o) x += t;
        }
        pref[c] = x - v;
        if (lane == 31) chunk_tot[c] = x;
    }
    __syncwarp();
    int base = 0;
    #pragma unroll
    for (int c = 0; c < 4; c++) {
        int i = c * 32 + lane;
        if (i < SCAN_NB) blockoff[i] = base + pref[c];
        base += chunk_tot[c];
    }
    if (lane == 0) rowstart[NN] = base;
}

__global__ void scan_p3(const int* __restrict__ cnt, const int* __restrict__ blockoff,
                        int* rowstart, int* cursor) {
    __shared__ int ws[8];
    __shared__ int s_run, s_tot;
    int b = blockIdx.x, tid = threadIdx.x, lane = tid & 31, w = tid >> 5;
    if (tid == 0) s_run = blockoff[b];
    __syncthreads();
    int cbase = b * SCAN_CH;
    for (int base = 0; base < SCAN_CH; base += 256) {
        int li = base + tid;
        int v = (li < SCAN_CH) ? cnt[cbase + li] : 0;
        int x = v;
        #pragma unroll
        for (int o = 1; o < 32; o <<= 1) {
            int t = __shfl_up_sync(0xFFFFFFFFu, x, o);
            if (lane >= o) x += t;
        }
        if (lane == 31) ws[w] = x;
        __syncthreads();
        if (tid == 0) {
            int s = 0;
            #pragma unroll
            for (int j = 0; j < 8; j++) { int t = ws[j]; ws[j] = s; s += t; }
            s_tot = s;
        }
        __syncthreads();
        int excl = s_run + ws[w] + x - v;
        if (li < SCAN_CH) { rowstart[cbase + li] = excl; cursor[cbase + li] = excl; }
        __syncthreads();
        if (tid == 0) s_run += s_tot;
        __syncthreads();
    }
}

__global__ void fill_kernel(const int* __restrict__ src, const int* __restrict__ dst,
                            const float* __restrict__ inv,
                            int* cursor, int2* edge) {
    int e = blockIdx.x * blockDim.x + threadIdx.x;
    if (e < EE) {
        int s = src[e], d = dst[e];
        int p = atomicAdd(&cursor[d], 1);
        edge[p] = make_int2(s, __float_as_int(inv[s] * inv[d]));
    }
}

// ---------------- fp32 -> bf16 convert ----------------
__global__ void cvt_bf16_kernel(const float* __restrict__ in, __nv_bfloat16* __restrict__ out,
                                int n4) {
    int i = blockIdx.x * blockDim.x + threadIdx.x;
    if (i < n4) {
        float4 v = *(const float4*)(in + (size_t)i * 4);
        *(__nv_bfloat162*)(out + (size_t)i * 4)     = __floats2bfloat162_rn(v.x, v.y);
        *(__nv_bfloat162*)(out + (size_t)i * 4 + 2) = __floats2bfloat162_rn(v.z, v.w);
    }
}

// ---------------- bf16-gather SpMM aggregation: one warp per node, 4-edge unroll ----
// fp32 accumulate; OUT16 selects bf16 vs fp32 output. F multiple of 64.
template <int F, int RELU, int BIAS, int OUT16>
__global__ void agg_bf16_kernel(const __nv_bfloat16* __restrict__ hin, void* __restrict__ outv,
                                const int* __restrict__ rowstart,
                                const int2* __restrict__ edge,
                                const float* __restrict__ inv, const float* __restrict__ bias) {
    int node = (blockIdx.x * blockDim.x + threadIdx.x) >> 5;
    int lane = threadIdx.x & 31;
    if (node >= NN) return;
    const int KC = F / 64;
    float2 acc[KC];
    float sn = inv[node]; sn *= sn;
    const __nv_bfloat16* hrow = hin + (size_t)node * F;
    #pragma unroll
    for (int k = 0; k < KC; k++) {
        float2 v = __bfloat1622float2(*(const __nv_bfloat162*)(hrow + lane * 2 + 64 * k));
        acc[k].x = v.x * sn;
        acc[k].y = v.y * sn;
    }
    int j = rowstart[node], end = rowstart[node + 1];
    for (; j + 3 < end; j += 4) {
        int2 e0 = __ldg(edge + j);
        int2 e1 = __ldg(edge + j + 1);
        int2 e2 = __ldg(edge + j + 2);
        int2 e3 = __ldg(edge + j + 3);
        const __nv_bfloat16* p0 = hin + (size_t)e0.x * F;
        const __nv_bfloat16* p1 = hin + (size_t)e1.x * F;
        const __nv_bfloat16* p2 = hin + (size_t)e2.x * F;
        const __nv_bfloat16* p3 = hin + (size_t)e3.x * F;
        __nv_bfloat162 v0[KC], v1[KC], v2[KC], v3[KC];
        #pragma unroll
        for (int k = 0; k < KC; k++) {
            int c = lane * 2 + 64 * k;
            v0[k] = *(const __nv_bfloat162*)(p0 + c);
            v1[k] = *(const __nv_bfloat162*)(p1 + c);
            v2[k] = *(const __nv_bfloat162*)(p2 + c);
            v3[k] = *(const __nv_bfloat162*)(p3 + c);
        }
        float c0 = __int_as_float(e0.y), c1 = __int_as_float(e1.y);
        float c2 = __int_as_float(e2.y), c3 = __int_as_float(e3.y);
        #pragma unroll
        for (int k = 0; k < KC; k++) {
            float2 f0 = __bfloat1622float2(v0[k]);
            float2 f1 = __bfloat1622float2(v1[k]);
            float2 f2 = __bfloat1622float2(v2[k]);
            float2 f3 = __bfloat1622float2(v3[k]);
            acc[k].x = fmaf(c0, f0.x, acc[k].x); acc[k].y = fmaf(c0, f0.y, acc[k].y);
            acc[k].x = fmaf(c1, f1.x, acc[k].x); acc[k].y = fmaf(c1, f1.y, acc[k].y);
            acc[k].x = fmaf(c2, f2.x, acc[k].x); acc[k].y = fmaf(c2, f2.y, acc[k].y);
            acc[k].x = fmaf(c3, f3.x, acc[k].x); acc[k].y = fmaf(c3, f3.y, acc[k].y);
        }
    }
    for (; j < end; j++) {
        int2 e = __ldg(edge + j);
        float cf = __int_as_float(e.y);
        const __nv_bfloat16* hs = hin + (size_t)e.x * F;
        #pragma unroll
        for (int k = 0; k < KC; k++) {
            float2 v = __bfloat1622float2(*(const __nv_bfloat162*)(hs + lane * 2 + 64 * k));
            acc[k].x = fmaf(cf, v.x, acc[k].x);
            acc[k].y = fmaf(cf, v.y, acc[k].y);
        }
    }
    #pragma unroll
    for (int k = 0; k < KC; k++) {
        int c = lane * 2 + 64 * k;
        float vx = acc[k].x + (BIAS ? bias[c] : 0.0f);
        float vy = acc[k].y + (BIAS ? bias[c + 1] : 0.0f);
        if (RELU) { vx = fmaxf(vx, 0.0f); vy = fmaxf(vy, 0.0f); }
        if (OUT16) {
            __nv_bfloat16* o = (__nv_bfloat16*)outv;
            *(__nv_bfloat162*)(o + (size_t)node * F + c) = __floats2bfloat162_rn(vx, vy);
        } else {
            float* o = (float*)outv;
            *(float2*)(o + (size_t)node * F + c) = make_float2(vx, vy);
        }
    }
}

// fp32 scalar agg (layer 4, F=40; protects logits)
template <int F, int RELU, int BIAS>
__global__ void agg_kernel(const float* __restrict__ hin, float* __restrict__ out,
                           const int* __restrict__ rowstart,
                           const int2* __restrict__ edge,
                           const float* __restrict__ inv, const float* __restrict__ bias) {
    int node = (blockIdx.x * blockDim.x + threadIdx.x) >> 5;
    int lane = threadIdx.x & 31;
    if (node >= NN) return;
    const int KC = (F + 31) / 32;
    float acc[KC];
    float sn = inv[node]; sn *= sn;
    const float* hrow = hin + (size_t)node * F;
    #pragma unroll
    for (int k = 0; k < KC; k++) {
        int c = lane + 32 * k;
        acc[k] = (c < F) ? hrow[c] * sn : 0.0f;
    }
    int j = rowstart[node], end = rowstart[node + 1];
    for (; j + 1 < end; j += 2) {
        int2 e0 = __ldg(edge + j);
        int2 e1 = __ldg(edge + j + 1);
        float c0 = __int_as_float(e0.y), c1 = __int_as_float(e1.y);
        const float* h0 = hin + (size_t)e0.x * F;
        const float* h1 = hin + (size_t)e1.x * F;
        #pragma unroll
        for (int k = 0; k < KC; k++) {
            int c = lane + 32 * k;
            if (c < F) {
                acc[k] = fmaf(c0, __ldg(h0 + c), acc[k]);
                acc[k] = fmaf(c1, __ldg(h1 + c), acc[k]);
            }
        }
    }
    if (j < end) {
        int2 e = __ldg(edge + j);
        float cf = __int_as_float(e.y);
        const float* hs = hin + (size_t)e.x * F;
        #pragma unroll
        for (int k = 0; k < KC; k++) {
            int c = lane + 32 * k;
            if (c < F) acc[k] = fmaf(cf, __ldg(hs + c), acc[k]);
        }
    }
    float* orow = out + (size_t)node * F;
    #pragma unroll
    for (int k = 0; k < KC; k++) {
        int c = lane + 32 * k;
        if (c < F) {
            float v = acc[k] + (BIAS ? bias[c] : 0.0f);
            if (RELU) v = fmaxf(v, 0.0f);
            orow[c] = v;
        }
    }
}

// ---------------- bf16 tensor-core GEMM (m16n8k16) ----------------
// C[M,Nn] = A[M,K](bf16) @ W[K,Nn](fp32, cvt in staging) (+bias)(+relu)
// BM=128, BN=128, BK=32, 256 threads (4m x 2n warps), warp tile 32m x 64n.
template <int RELU, int BIAS, int BF16OUT>
__global__ void __launch_bounds__(256)
gemm_bf16_kernel(const __nv_bfloat16* __restrict__ A, const float* __restrict__ W,
                 const float* __restrict__ bias, void* __restrict__ Cv,
                 int M, int K, int Nn) {
    __shared__ __align__(16) __nv_bfloat16 As[128][40];   // [m][k], pad to 40
    __shared__ __align__(16) __nv_bfloat16 Bs[128][40];   // [n][k] (transposed)
    int tid = threadIdx.x;
    int wid = tid >> 5, lane = tid & 31;
    int gid = lane >> 2, tig = lane & 3;
    int m0 = blockIdx.y * 128;
    int n0 = blockIdx.x * 128;
    int mbase = (wid >> 1) * 32;
    int nbase = (wid & 1) * 64;

    float acc[2][8][4];
    #pragma unroll
    for (int mt = 0; mt < 2; mt++)
        #pragma unroll
        for (int nt = 0; nt < 8; nt++)
            #pragma unroll
            for (int q = 0; q < 4; q++) acc[mt][nt][q] = 0.0f;

    for (int k0 = 0; k0 < K; k0 += 32) {
        // stage A: 128 x 32 bf16, 16B per thread x2
        #pragma unroll
        for (int t = 0; t < 2; t++) {
            int idx = tid + t * 256;
            int r = idx >> 2, c8 = idx & 3;       // row, 8-elem chunk
            int gr = m0 + r;
            uint4 v = make_uint4(0u, 0u, 0u, 0u);
            if (gr < M) v = *(const uint4*)(A + (size_t)gr * K + k0 + c8 * 8);
            *(uint4*)&As[r][c8 * 8] = v;
        }
        // stage B: W[k0+r][n0+c*4..+3] fp32 -> Bs[n][k] bf16 (transpose + cvt)
        #pragma unroll
        for (int t = 0; t < 4; t++) {
            int idx = tid + t * 256;
            int r = idx >> 5, c = idx & 31;
            int gn = n0 + c * 4;
            float4 v = make_float4(0.f, 0.f, 0.f, 0.f);
            if (gn + 3 < Nn) {
                v = *(const float4*)(W + (size_t)(k0 + r) * Nn + gn);
            } else if (gn < Nn) {
                const float* wr = W + (size_t)(k0 + r) * Nn;
                v.x = wr[gn];
                if (gn + 1 < Nn) v.y = wr[gn + 1];
                if (gn + 2 < Nn) v.z = wr[gn + 2];
            }
            Bs[c * 4 + 0][r] = __float2bfloat16(v.x);
            Bs[c * 4 + 1][r] = __float2bfloat16(v.y);
            Bs[c * 4 + 2][r] = __float2bfloat16(v.z);
            Bs[c * 4 + 3][r] = __float2bfloat16(v.w);
        }
        __syncthreads();

        #pragma unroll
        for (int kk = 0; kk < 2; kk++) {
            int kf = kk * 16;
            unsigned af[2][4], bf[8][2];
            #pragma unroll
            for (int mt = 0; mt < 2; mt++) {
                int mr = mbase + mt * 16 + gid;
                af[mt][0] = *(const unsigned*)&As[mr][kf + tig * 2];
                af[mt][1] = *(const unsigned*)&As[mr + 8][kf + tig * 2];
                af[mt][2] = *(const unsigned*)&As[mr][kf + tig * 2 + 8];
                af[mt][3] = *(const unsigned*)&As[mr + 8][kf + tig * 2 + 8];
            }
            #pragma unroll
            for (int nt = 0; nt < 8; nt++) {
                int nc = nbase + nt * 8 + gid;
                bf[nt][0] = *(const unsigned*)&Bs[nc][kf + tig * 2];
                bf[nt][1] = *(const unsigned*)&Bs[nc][kf + tig * 2 + 8];
            }
            #pragma unroll
            for (int mt = 0; mt < 2; mt++)
                #pragma unroll
                for (int nt = 0; nt < 8; nt++) {
                    asm volatile(
                        "mma.sync.aligned.m16n8k16.row.col.f32.bf16.bf16.f32 "
                        "{%0,%1,%2,%3},{%4,%5,%6,%7},{%8,%9},{%0,%1,%2,%3};"
                        : "+f"(acc[mt][nt][0]), "+f"(acc[mt][nt][1]),
                          "+f"(acc[mt][nt][2]), "+f"(acc[mt][nt][3])
                        : "r"(af[mt][0]), "r"(af[mt][1]), "r"(af[mt][2]), "r"(af[mt][3]),
                          "r"(bf[nt][0]), "r"(bf[nt][1]));
                }
        }
        __syncthreads();
    }

    // epilogue
    #pragma unroll
    for (int mt = 0; mt < 2; mt++) {
        int row0 = m0 + mbase + mt * 16 + gid;
        #pragma unroll
        for (int nt = 0; nt < 8; nt++) {
            int col0 = n0 + nbase + nt * 8 + tig * 2;
            #pragma unroll
            for (int h = 0; h < 2; h++) {
                int r = row0 + h * 8;
                if (r >= M) continue;
                float b0 = (BIAS && col0 < Nn) ? bias[col0] : 0.f;
                float b1 = (BIAS && col0 + 1 < Nn) ? bias[col0 + 1] : 0.f;
                float v0 = acc[mt][nt][h * 2 + 0] + b0;
                float v1 = acc[mt][nt][h * 2 + 1] + b1;
                if (RELU) { v0 = fmaxf(v0, 0.f); v1 = fmaxf(v1, 0.f); }
                if (BF16OUT) {
                    __nv_bfloat16* Cb = (__nv_bfloat16*)Cv;
                    if (col0 + 1 < Nn) {
                        *(__nv_bfloat162*)(Cb + (size_t)r * Nn + col0) =
                            __floats2bfloat162_rn(v0, v1);
                    } else if (col0 < Nn) {
                        Cb[(size_t)r * Nn + col0] = __float2bfloat16(v0);
                    }
                } else {
                    float* Cf = (float*)Cv;
                    if (col0 < Nn) Cf[(size_t)r * Nn + col0] = v0;
                    if (col0 + 1 < Nn) Cf[(size_t)r * Nn + col0 + 1] = v1;
                }
            }
        }
    }
}

// ---------------- log_softmax over 40 cols, one warp per row ----------------
__global__ void lsm_kernel(const float* __restrict__ z, float* __restrict__ out) {
    int row = (blockIdx.x * blockDim.x + threadIdx.x) >> 5;
    int lane = threadIdx.x & 31;
    if (row >= NN) return;
    const float* zr = z + (size_t)row * NC;
    float v0 = (lane < NC) ? zr[lane] : -1e30f;
    float v1 = (lane + 32 < NC) ? zr[lane + 32] : -1e30f;
    float m = fmaxf(v0, v1);
    #pragma unroll
    for (int o = 16; o > 0; o >>= 1) m = fmaxf(m, __shfl_xor_sync(0xFFFFFFFFu, m, o));
    float s = ((lane < NC) ? expf(v0 - m) : 0.0f) + ((lane + 32 < NC) ? expf(v1 - m) : 0.0f);
    #pragma unroll
    for (int o = 16; o > 0; o >>= 1) s += __shfl_xor_sync(0xFFFFFFFFu, s, o);
    float lse = m + logf(s);
    float* orow = out + (size_t)row * NC;
    if (lane < NC) orow[lane] = v0 - lse;
    if (lane + 32 < NC) orow[lane + 32] = v1 - lse;
}

// ---------------- host launch ----------------
extern "C" void kernel_launch(void* const* d_in, const int* in_sizes, int n_in,
                              void* d_out, int out_size) {
    const float* x  = (const float*)d_in[0];
    const int*   ei = (const int*)d_in[1];
    const float* W1 = (const float*)d_in[2];
    const float* b1 = (const float*)d_in[3];
    const float* W2 = (const float*)d_in[4];
    const float* b2 = (const float*)d_in[5];
    const float* W3 = (const float*)d_in[6];
    const float* b3 = (const float*)d_in[7];
    const float* W4 = (const float*)d_in[8];
    const float* b4 = (const float*)d_in[9];
    float* out = (float*)d_out;

    const int* src = ei;
    const int* dst = ei + EE;

    float *inv, *h, *a;
    int *cnt, *rowstart, *cursor, *partial, *blockoff;
    int2* edge;
    __nv_bfloat16 *xb, *axb, *p, *q;
    cudaGetSymbolAddress((void**)&inv, g_inv);
    cudaGetSymbolAddress((void**)&cnt, g_cnt);
    cudaGetSymbolAddress((void**)&rowstart, g_rowstart);
    cudaGetSymbolAddress((void**)&cursor, g_cursor);
    cudaGetSymbolAddress((void**)&edge, g_edge);
    cudaGetSymbolAddress((void**)&partial, g_partial);
    cudaGetSymbolAddress((void**)&blockoff, g_blockoff);
    cudaGetSymbolAddress((void**)&xb, g_xb);
    cudaGetSymbolAddress((void**)&axb, g_axb);
    cudaGetSymbolAddress((void**)&p, g_p);
    cudaGetSymbolAddress((void**)&q, g_q);
    cudaGetSymbolAddress((void**)&h, g_h);
    cudaGetSymbolAddress((void**)&a, g_a);

    const int TPB = 256;
    int gN = (NN + TPB - 1) / TPB;
    int gE = (EE + TPB - 1) / TPB;
    int gWarp1 = (NN * 32 + TPB - 1) / TPB;   // 1 warp/node
    int nX4 = NN * FIN / 4;
    int gX4 = (nX4 + TPB - 1) / TPB;

    // graph preprocessing (CSR by dst)
    init_kernel<<<gN, TPB>>>(cnt);
    count_kernel<<<gE, TPB>>>(dst, cnt);
    inv_kernel<<<gN, TPB>>>(cnt, inv);
    scan_p1<<<SCAN_NB, 256>>>(cnt, partial);
    scan_p2<<<1, 32>>>(partial, blockoff, rowstart);
    scan_p3<<<SCAN_NB, 256>>>(cnt, blockoff, rowstart, cursor);
    fill_kernel<<<gE, TPB>>>(src, dst, inv, cursor, edge);

    // x -> bf16
    cvt_bf16_kernel<<<gX4, TPB>>>(x, xb, nX4);

    dim3 gridHID(2, (NN + 127) / 128);   // N=256
    dim3 gridC(1, (NN + 127) / 128);     // N=40

    // Layer 1: agg(xb) -> bf16, GEMM(+b1,relu) -> bf16 p
    agg_bf16_kernel<FIN, 0, 0, 1><<<gWarp1, TPB>>>(xb, axb, rowstart, edge, inv, nullptr);
    gemm_bf16_kernel<1, 1, 1><<<gridHID, TPB>>>(axb, W1, b1, p, NN, FIN, HID);

    // Layer 2: GEMM -> bf16 q, agg(+b2,relu) -> bf16 p
    gemm_bf16_kernel<0, 0, 1><<<gridHID, TPB>>>(p, W2, nullptr, q, NN, HID, HID);
    agg_bf16_kernel<HID, 1, 1, 1><<<gWarp1, TPB>>>(q, p, rowstart, edge, inv, b2);

    // Layer 3
    gemm_bf16_kernel<0, 0, 1><<<gridHID, TPB>>>(p, W3, nullptr, q, NN, HID, HID);
    agg_bf16_kernel<HID, 1, 1, 1><<<gWarp1, TPB>>>(q, p, rowstart, edge, inv, b3);

    // Layer 4: fp32 logits path
    gemm_bf16_kernel<0, 0, 0><<<gridC, TPB>>>(p, W4, nullptr, h, NN, HID, NC);
    agg_kernel<NC, 0, 1><<<gWarp1, TPB>>>(h, a, rowstart, edge, inv, b4);
    lsm_kernel<<<gWarp1, TPB>>>(a, out);
}

// round 10
// speedup vs baseline: 2.3517x; 1.4784x over previous
#include <cuda_runtime.h>
#include <cuda_bf16.h>
#include <math.h>

#define NN 50000
#define EE 1600000
#define FIN 128
#define HID 256
#define NC 40

#define SCAN_NB 100
#define SCAN_CH 500   // SCAN_NB * SCAN_CH == NN

// ---------------- scratch (device globals; no allocation) ----------------
__device__ float g_inv[NN];
__device__ int   g_cnt[NN];
__device__ int   g_rowstart[NN + 1];
__device__ int   g_cursor[NN];
__device__ int   g_partial[SCAN_NB];
__device__ int2  g_edge[EE];                        // {src, coef bits}
__device__ __nv_bfloat16 g_xb [(size_t)NN * FIN];   // bf16 x
__device__ __nv_bfloat16 g_axb[(size_t)NN * FIN];   // bf16 agg(x)
__device__ __nv_bfloat16 g_p  [(size_t)NN * HID];   // bf16 ping
__device__ __nv_bfloat16 g_q  [(size_t)NN * HID];   // bf16 pong
__device__ float g_h[(size_t)NN * 64];              // fp32 layer-4 logits
__device__ __nv_bfloat16 g_w1t[HID * FIN];          // W1^T bf16 [256][128]
__device__ __nv_bfloat16 g_w2t[HID * HID];          // W2^T bf16 [256][256]
__device__ __nv_bfloat16 g_w3t[HID * HID];          // W3^T bf16
__device__ __nv_bfloat16 g_w4t[NC * HID];           // W4^T bf16 [40][256]

// ---------------- cp.async helpers ----------------
__device__ __forceinline__ void cp_async16(void* smem, const void* gmem, bool pred) {
    unsigned s = (unsigned)__cvta_generic_to_shared(smem);
    int sz = pred ? 16 : 0;
    asm volatile("cp.async.ca.shared.global [%0], [%1], 16, %2;"
                 :: "r"(s), "l"(gmem), "r"(sz));
}
__device__ __forceinline__ void cp_commit() {
    asm volatile("cp.async.commit_group;");
}
template <int N>
__device__ __forceinline__ void cp_wait() {
    asm volatile("cp.async.wait_group %0;" :: "n"(N));
}

// ---------------- graph preprocessing ----------------
__global__ void init_kernel(int* cnt) {
    int i = blockIdx.x * blockDim.x + threadIdx.x;
    if (i < NN) cnt[i] = 0;
}

__global__ void count_kernel(const int* __restrict__ dst, int* cnt) {
    int e = blockIdx.x * blockDim.x + threadIdx.x;
    if (e < EE) atomicAdd(&cnt[dst[e]], 1);
}

// per-block partial sums of cnt chunks + inv = rsqrt(deg) fused
__global__ void scan_p1_inv(const int* __restrict__ cnt, int* partial, float* inv) {
    __shared__ int ws[8];
    int b = blockIdx.x, tid = threadIdx.x;
    int base = b * SCAN_CH;
    int s = 0;
    for (int i = tid; i < SCAN_CH; i += 256) {
        int c = cnt[base + i];
        s += c;
        inv[base + i] = rsqrtf((float)c + 1.0f);   // +1 self-loop
    }
    #pragma unroll
    for (int o = 16; o > 0; o >>= 1) s += __shfl_xor_sync(0xFFFFFFFFu, s, o);
    if ((tid & 31) == 0) ws[tid >> 5] = s;
    __syncthreads();
    if (tid == 0) {
        int t = 0;
        #pragma unroll
        for (int j = 0; j < 8; j++) t += ws[j];
        partial[b] = t;
    }
}

// fused: each block derives its own offset from partials, then local scan
__global__ void scan_p23(const int* __restrict__ partial, const int* __restrict__ cnt,
                         int* rowstart, int* cursor) {
    __shared__ int ws[8];
    __shared__ int s_run, s_tot;
    int b = blockIdx.x, tid = threadIdx.x, lane = tid & 31, w = tid >> 5;
    if (tid < 32) {
        int s = 0;
        for (int i = lane; i < b; i += 32) s += partial[i];
        #pragma unroll
        for (int o = 16; o > 0; o >>= 1) s += __shfl_xor_sync(0xFFFFFFFFu, s, o);
        if (lane == 0) s_run = s;
    }
    __syncthreads();
    int cbase = b * SCAN_CH;
    for (int base = 0; base < SCAN_CH; base += 256) {
        int li = base + tid;
        int v = (li < SCAN_CH) ? cnt[cbase + li] : 0;
        int x = v;
        #pragma unroll
        for (int o = 1; o < 32; o <<= 1) {
            int t = __shfl_up_sync(0xFFFFFFFFu, x, o);
            if (lane >= o) x += t;
        }
        if (lane == 31) ws[w] = x;
        __syncthreads();
        if (tid == 0) {
            int s = 0;
            #pragma unroll
            for (int j = 0; j < 8; j++) { int t = ws[j]; ws[j] = s; s += t; }
            s_tot = s;
        }
        __syncthreads();
        int excl = s_run + ws[w] + x - v;
        if (li < SCAN_CH) { rowstart[cbase + li] = excl; cursor[cbase + li] = excl; }
        __syncthreads();
        if (tid == 0) s_run += s_tot;
        __syncthreads();
    }
    if (b == SCAN_NB - 1 && tid == 0) rowstart[NN] = s_run;
}

// fill CSR edges + convert x to bf16 (same 1.6M-thread grid)
__global__ void fill_cvt_kernel(const int* __restrict__ src, const int* __restrict__ dst,
                                const float* __restrict__ inv, int* cursor, int2* edge,
                                const float* __restrict__ x, __nv_bfloat16* __restrict__ xb) {
    int e = blockIdx.x * blockDim.x + threadIdx.x;
    if (e < EE) {
        int s = src[e], d = dst[e];
        int p = atomicAdd(&cursor[d], 1);
        edge[p] = make_int2(s, __float_as_int(inv[s] * inv[d]));
    }
    if (e < NN * FIN / 4) {
        float4 v = *(const float4*)(x + (size_t)e * 4);
        *(__nv_bfloat162*)(xb + (size_t)e * 4)     = __floats2bfloat162_rn(v.x, v.y);
        *(__nv_bfloat162*)(xb + (size_t)e * 4 + 2) = __floats2bfloat162_rn(v.z, v.w);
    }
}

// transpose+convert all weights to bf16 [N][K]
__global__ void cvtW_kernel(const float* __restrict__ W1, const float* __restrict__ W2,
                            const float* __restrict__ W3, const float* __restrict__ W4,
                            __nv_bfloat16* T1, __nv_bfloat16* T2,
                            __nv_bfloat16* T3, __nv_bfloat16* T4) {
    int i = blockIdx.x * blockDim.x + threadIdx.x;
    if (i < 32768) {                               // W1: [128][256] -> T1 [256][128]
        int n = i / 128, k = i % 128;
        T1[i] = __float2bfloat16(W1[(size_t)k * 256 + n]);
    } else if (i < 98304) {                        // W2: [256][256]
        int j = i - 32768; int n = j / 256, k = j % 256;
        T2[j] = __float2bfloat16(W2[(size_t)k * 256 + n]);
    } else if (i < 163840) {                       // W3
        int j = i - 98304; int n = j / 256, k = j % 256;
        T3[j] = __float2bfloat16(W3[(size_t)k * 256 + n]);
    } else if (i < 174080) {                       // W4: [256][40] -> T4 [40][256]
        int j = i - 163840; int n = j / 256, k = j % 256;
        T4[j] = __float2bfloat16(W4[(size_t)k * 40 + n]);
    }
}

// ---------------- vectorized bf16 SpMM aggregation ----------------
// Lane owns F/32 CONTIGUOUS columns -> one 8/16B load per edge per lane.
template <int NH>
__device__ __forceinline__ void ldrow(__nv_bfloat162* b, const __nv_bfloat16* p) {
    if (NH == 4) {
        uint4 v = *(const uint4*)p;
        b[0] = ((const __nv_bfloat162*)&v)[0];
        b[1] = ((const __nv_bfloat162*)&v)[1];
        b[2] = ((const __nv_bfloat162*)&v)[2];
        b[3] = ((const __nv_bfloat162*)&v)[3];
    } else {
        uint2 v = *(const uint2*)p;
        b[0] = ((const __nv_bfloat162*)&v)[0];
        b[1] = ((const __nv_bfloat162*)&v)[1];
    }
}

template <int F, int RELU, int BIAS>
__global__ void agg_v_kernel(const __nv_bfloat16* __restrict__ hin,
                             __nv_bfloat16* __restrict__ out,
                             const int* __restrict__ rowstart,
                             const int2* __restrict__ edge,
                             const float* __restrict__ inv, const float* __restrict__ bias) {
    int node = (blockIdx.x * blockDim.x + threadIdx.x) >> 5;
    int lane = threadIdx.x & 31;
    if (node >= NN) return;
    const int NV = F / 32;       // cols per lane: 4 (F=128) / 8 (F=256)
    const int NH = NV / 2;       // bf162 per lane
    int coff = lane * NV;
    float acc[NV];
    float sn = inv[node]; sn *= sn;
    {
        __nv_bfloat162 b[NH];
        ldrow<NH>(b, hin + (size_t)node * F + coff);
        #pragma unroll
        for (int h = 0; h < NH; h++) {
            float2 f = __bfloat1622float2(b[h]);
            acc[2 * h]     = f.x * sn;
            acc[2 * h + 1] = f.y * sn;
        }
    }
    int j = rowstart[node], end = rowstart[node + 1];
    for (; j + 3 < end; j += 4) {
        int2 e0 = __ldg(edge + j);
        int2 e1 = __ldg(edge + j + 1);
        int2 e2 = __ldg(edge + j + 2);
        int2 e3 = __ldg(edge + j + 3);
        __nv_bfloat162 b0[NH], b1[NH], b2[NH], b3[NH];
        ldrow<NH>(b0, hin + (size_t)e0.x * F + coff);
        ldrow<NH>(b1, hin + (size_t)e1.x * F + coff);
        ldrow<NH>(b2, hin + (size_t)e2.x * F + coff);
        ldrow<NH>(b3, hin + (size_t)e3.x * F + coff);
        float c0 = __int_as_float(e0.y), c1 = __int_as_float(e1.y);
        float c2 = __int_as_float(e2.y), c3 = __int_as_float(e3.y);
        #pragma unroll
        for (int h = 0; h < NH; h++) {
            float2 f0 = __bfloat1622float2(b0[h]);
            float2 f1 = __bfloat1622float2(b1[h]);
            float2 f2 = __bfloat1622float2(b2[h]);
            float2 f3 = __bfloat1622float2(b3[h]);
            acc[2*h]   = fmaf(c0, f0.x, acc[2*h]);   acc[2*h+1] = fmaf(c0, f0.y, acc[2*h+1]);
            acc[2*h]   = fmaf(c1, f1.x, acc[2*h]);   acc[2*h+1] = fmaf(c1, f1.y, acc[2*h+1]);
            acc[2*h]   = fmaf(c2, f2.x, acc[2*h]);   acc[2*h+1] = fmaf(c2, f2.y, acc[2*h+1]);
            acc[2*h]   = fmaf(c3, f3.x, acc[2*h]);   acc[2*h+1] = fmaf(c3, f3.y, acc[2*h+1]);
        }
    }
    for (; j < end; j++) {
        int2 e = __ldg(edge + j);
        float cf = __int_as_float(e.y);
        __nv_bfloat162 b[NH];
        ldrow<NH>(b, hin + (size_t)e.x * F + coff);
        #pragma unroll
        for (int h = 0; h < NH; h++) {
            float2 f = __bfloat1622float2(b[h]);
            acc[2*h]   = fmaf(cf, f.x, acc[2*h]);
            acc[2*h+1] = fmaf(cf, f.y, acc[2*h+1]);
        }
    }
    // bias + relu + pack + single vector store
    __nv_bfloat162 ob[NH];
    #pragma unroll
    for (int h = 0; h < NH; h++) {
        float vx = acc[2*h]   + (BIAS ? bias[coff + 2*h]     : 0.0f);
        float vy = acc[2*h+1] + (BIAS ? bias[coff + 2*h + 1] : 0.0f);
        if (RELU) { vx = fmaxf(vx, 0.0f); vy = fmaxf(vy, 0.0f); }
        ob[h] = __floats2bfloat162_rn(vx, vy);
    }
    __nv_bfloat16* o = out + (size_t)node * F + coff;
    if (NH == 4) {
        uint4 v;
        ((__nv_bfloat162*)&v)[0] = ob[0]; ((__nv_bfloat162*)&v)[1] = ob[1];
        ((__nv_bfloat162*)&v)[2] = ob[2]; ((__nv_bfloat162*)&v)[3] = ob[3];
        *(uint4*)o = v;
    } else {
        uint2 v;
        ((__nv_bfloat162*)&v)[0] = ob[0]; ((__nv_bfloat162*)&v)[1] = ob[1];
        *(uint2*)o = v;
    }
}

// fused layer-4 aggregation (fp32, F=40) + log_softmax
__global__ void agg_lsm_kernel(const float* __restrict__ hin, float* __restrict__ out,
                               const int* __restrict__ rowstart,
                               const int2* __restrict__ edge,
                               const float* __restrict__ inv, const float* __restrict__ bias) {
    int node = (blockIdx.x * blockDim.x + threadIdx.x) >> 5;
    int lane = threadIdx.x & 31;
    if (node >= NN) return;
    float sn = inv[node]; sn *= sn;
    const float* hrow = hin + (size_t)node * NC;
    float a0 = hrow[lane] * sn;                       // lane < 32 < 40, always valid
    float a1 = (lane < 8) ? hrow[lane + 32] * sn : 0.0f;
    int j = rowstart[node], end = rowstart[node + 1];
    for (; j + 1 < end; j += 2) {
        int2 e0 = __ldg(edge + j);
        int2 e1 = __ldg(edge + j + 1);
        float c0 = __int_as_float(e0.y), c1 = __int_as_float(e1.y);
        const float* h0 = hin + (size_t)e0.x * NC;
        const float* h1 = hin + (size_t)e1.x * NC;
        a0 = fmaf(c0, __ldg(h0 + lane), a0);
        a0 = fmaf(c1, __ldg(h1 + lane), a0);
        if (lane < 8) {
            a1 = fmaf(c0, __ldg(h0 + lane + 32), a1);
            a1 = fmaf(c1, __ldg(h1 + lane + 32), a1);
        }
    }
    if (j < end) {
        int2 e = __ldg(edge + j);
        float cf = __int_as_float(e.y);
        const float* hs = hin + (size_t)e.x * NC;
        a0 = fmaf(cf, __ldg(hs + lane), a0);
        if (lane < 8) a1 = fmaf(cf, __ldg(hs + lane + 32), a1);
    }
    a0 += bias[lane];
    if (lane < 8) a1 += bias[lane + 32];
    // log_softmax over the 40 logits held in-warp
    float v1m = (lane < 8) ? a1 : -1e30f;
    float m = fmaxf(a0, v1m);
    #pragma unroll
    for (int o = 16; o > 0; o >>= 1) m = fmaxf(m, __shfl_xor_sync(0xFFFFFFFFu, m, o));
    float s = expf(a0 - m) + ((lane < 8) ? expf(a1 - m) : 0.0f);
    #pragma unroll
    for (int o = 16; o > 0; o >>= 1) s += __shfl_xor_sync(0xFFFFFFFFu, s, o);
    float lse = m + logf(s);
    float* orow = out + (size_t)node * NC;
    orow[lane] = a0 - lse;
    if (lane < 8) orow[lane + 32] = a1 - lse;
}

// ---------------- bf16 tensor-core GEMM, 2-stage cp.async pipeline ----------------
// C[M,Nn] = A[M,K](bf16) @ WT[Nn,K](bf16) (+bias)(+relu)
// BM=128, BN=128, BK=32, 256 threads (4m x 2n warps), warp tile 32m x 64n.
template <int RELU, int BIAS, int BF16OUT>
__global__ void __launch_bounds__(256)
gemm_bf16_kernel(const __nv_bfloat16* __restrict__ A, const __nv_bfloat16* __restrict__ WT,
                 const float* __restrict__ bias, void* __restrict__ Cv,
                 int M, int K, int Nn) {
    __shared__ __align__(16) __nv_bfloat16 As[2][128][40];
    __shared__ __align__(16) __nv_bfloat16 Bs[2][128][40];
    int tid = threadIdx.x;
    int wid = tid >> 5, lane = tid & 31;
    int gid = lane >> 2, tig = lane & 3;
    int m0 = blockIdx.y * 128;
    int n0 = blockIdx.x * 128;
    int mbase = (wid >> 1) * 32;
    int nbase = (wid & 1) * 64;
    int NIT = K >> 5;

    float acc[2][8][4];
    #pragma unroll
    for (int mt = 0; mt < 2; mt++)
        #pragma unroll
        for (int nt = 0; nt < 8; nt++)
            #pragma unroll
            for (int q = 0; q < 4; q++) acc[mt][nt][q] = 0.0f;

    // staging: 512 16B chunks per operand, 256 threads -> 2 chunks each
    int rA = tid >> 2, cA = tid & 3;          // chunk 0 mapping (idx = tid)
    int rA2 = (tid + 256) >> 2, cA2 = (tid + 256) & 3;

    auto stage = [&](int st, int k0) {
        // A chunks
        cp_async16(&As[st][rA][cA * 8],
                   A + (size_t)(m0 + rA) * K + k0 + cA * 8, (m0 + rA) < M);
        cp_async16(&As[st][rA2][cA2 * 8],
                   A + (size_t)(m0 + rA2) * K + k0 + cA2 * 8, (m0 + rA2) < M);
        // B chunks (WT rows)
        cp_async16(&Bs[st][rA][cA * 8],
                   WT + (size_t)(n0 + rA) * K + k0 + cA * 8, (n0 + rA) < Nn);
        cp_async16(&Bs[st][rA2][cA2 * 8],
                   WT + (size_t)(n0 + rA2) * K + k0 + cA2 * 8, (n0 + rA2) < Nn);
    };

    stage(0, 0);
    cp_commit();

    for (int it = 0; it < NIT; it++) {
        if (it + 1 < NIT) {
            stage((it + 1) & 1, (it + 1) * 32);
            cp_commit();
            cp_wait<1>();
        } else {
            cp_wait<0>();
        }
        __syncthreads();
        int st = it & 1;
        #pragma unroll
        for (int kk = 0; kk < 2; kk++) {
            int kf = kk * 16;
            unsigned af[2][4], bf[8][2];
            #pragma unroll
            for (int mt = 0; mt < 2; mt++) {
                int mr = mbase + mt * 16 + gid;
                af[mt][0] = *(const unsigned*)&As[st][mr][kf + tig * 2];
                af[mt][1] = *(const unsigned*)&As[st][mr + 8][kf + tig * 2];
                af[mt][2] = *(const unsigned*)&As[st][mr][kf + tig * 2 + 8];
                af[mt][3] = *(const unsigned*)&As[st][mr + 8][kf + tig * 2 + 8];
            }
            #pragma unroll
            for (int nt = 0; nt < 8; nt++) {
                int nc = nbase + nt * 8 + gid;
                bf[nt][0] = *(const unsigned*)&Bs[st][nc][kf + tig * 2];
                bf[nt][1] = *(const unsigned*)&Bs[st][nc][kf + tig * 2 + 8];
            }
            #pragma unroll
            for (int mt = 0; mt < 2; mt++)
                #pragma unroll
                for (int nt = 0; nt < 8; nt++) {
                    asm volatile(
                        "mma.sync.aligned.m16n8k16.row.col.f32.bf16.bf16.f32 "
                        "{%0,%1,%2,%3},{%4,%5,%6,%7},{%8,%9},{%0,%1,%2,%3};"
                        : "+f"(acc[mt][nt][0]), "+f"(acc[mt][nt][1]),
                          "+f"(acc[mt][nt][2]), "+f"(acc[mt][nt][3])
                        : "r"(af[mt][0]), "r"(af[mt][1]), "r"(af[mt][2]), "r"(af[mt][3]),
                          "r"(bf[nt][0]), "r"(bf[nt][1]));
                }
        }
        __syncthreads();
    }

    // epilogue
    #pragma unroll
    for (int mt = 0; mt < 2; mt++) {
        int row0 = m0 + mbase + mt * 16 + gid;
        #pragma unroll
        for (int nt = 0; nt < 8; nt++) {
            int col0 = n0 + nbase + nt * 8 + tig * 2;
            #pragma unroll
            for (int h = 0; h < 2; h++) {
                int r = row0 + h * 8;
                if (r >= M) continue;
                float b0 = (BIAS && col0 < Nn) ? bias[col0] : 0.f;
                float b1 = (BIAS && col0 + 1 < Nn) ? bias[col0 + 1] : 0.f;
                float v0 = acc[mt][nt][h * 2 + 0] + b0;
                float v1 = acc[mt][nt][h * 2 + 1] + b1;
                if (RELU) { v0 = fmaxf(v0, 0.f); v1 = fmaxf(v1, 0.f); }
                if (BF16OUT) {
                    __nv_bfloat16* Cb = (__nv_bfloat16*)Cv;
                    if (col0 + 1 < Nn) {
                        *(__nv_bfloat162*)(Cb + (size_t)r * Nn + col0) =
                            __floats2bfloat162_rn(v0, v1);
                    } else if (col0 < Nn) {
                        Cb[(size_t)r * Nn + col0] = __float2bfloat16(v0);
                    }
                } else {
                    float* Cf = (float*)Cv;
                    if (col0 < Nn) Cf[(size_t)r * Nn + col0] = v0;
                    if (col0 + 1 < Nn) Cf[(size_t)r * Nn + col0 + 1] = v1;
                }
            }
        }
    }
}

// ---------------- host launch ----------------
extern "C" void kernel_launch(void* const* d_in, const int* in_sizes, int n_in,
                              void* d_out, int out_size) {
    const float* x  = (const float*)d_in[0];
    const int*   ei = (const int*)d_in[1];
    const float* W1 = (const float*)d_in[2];
    const float* b1 = (const float*)d_in[3];
    const float* W2 = (const float*)d_in[4];
    const float* b2 = (const float*)d_in[5];
    const float* W3 = (const float*)d_in[6];
    const float* b3 = (const float*)d_in[7];
    const float* W4 = (const float*)d_in[8];
    const float* b4 = (const float*)d_in[9];
    float* out = (float*)d_out;

    const int* src = ei;
    const int* dst = ei + EE;

    float *inv, *h;
    int *cnt, *rowstart, *cursor, *partial;
    int2* edge;
    __nv_bfloat16 *xb, *axb, *p, *q, *w1t, *w2t, *w3t, *w4t;
    cudaGetSymbolAddress((void**)&inv, g_inv);
    cudaGetSymbolAddress((void**)&cnt, g_cnt);
    cudaGetSymbolAddress((void**)&rowstart, g_rowstart);
    cudaGetSymbolAddress((void**)&cursor, g_cursor);
    cudaGetSymbolAddress((void**)&edge, g_edge);
    cudaGetSymbolAddress((void**)&partial, g_partial);
    cudaGetSymbolAddress((void**)&xb, g_xb);
    cudaGetSymbolAddress((void**)&axb, g_axb);
    cudaGetSymbolAddress((void**)&p, g_p);
    cudaGetSymbolAddress((void**)&q, g_q);
    cudaGetSymbolAddress((void**)&h, g_h);
    cudaGetSymbolAddress((void**)&w1t, g_w1t);
    cudaGetSymbolAddress((void**)&w2t, g_w2t);
    cudaGetSymbolAddress((void**)&w3t, g_w3t);
    cudaGetSymbolAddress((void**)&w4t, g_w4t);

    const int TPB = 256;
    int gN = (NN + TPB - 1) / TPB;
    int gE = (EE + TPB - 1) / TPB;
    int gWarp1 = (NN * 32 + TPB - 1) / TPB;   // 1 warp/node
    int gW = (174080 + TPB - 1) / TPB;

    // preprocessing (5 launches; heavy agg lands at profile slot 5)
    init_kernel<<<gN, TPB>>>(cnt);                                          // 0
    count_kernel<<<gE, TPB>>>(dst, cnt);                                    // 1
    scan_p1_inv<<<SCAN_NB, 256>>>(cnt, partial, inv);                       // 2
    scan_p23<<<SCAN_NB, 256>>>(partial, cnt, rowstart, cursor);             // 3
    fill_cvt_kernel<<<gE, TPB>>>(src, dst, inv, cursor, edge, x, xb);       // 4

    dim3 gridHID(2, (NN + 127) / 128);
    dim3 gridC(1, (NN + 127) / 128);

    // Layer 1
    agg_v_kernel<FIN, 0, 0><<<gWarp1, TPB>>>(xb, axb, rowstart, edge, inv, nullptr);  // 5 (profiled)
    cvtW_kernel<<<gW, TPB>>>(W1, W2, W3, W4, w1t, w2t, w3t, w4t);                     // 6
    gemm_bf16_kernel<1, 1, 1><<<gridHID, TPB>>>(axb, w1t, b1, p, NN, FIN, HID);       // 7

    // Layer 2
    gemm_bf16_kernel<0, 0, 1><<<gridHID, TPB>>>(p, w2t, nullptr, q, NN, HID, HID);    // 8
    agg_v_kernel<HID, 1, 1><<<gWarp1, TPB>>>(q, p, rowstart, edge, inv, b2);          // 9

    // Layer 3
    gemm_bf16_kernel<0, 0, 1><<<gridHID, TPB>>>(p, w3t, nullptr, q, NN, HID, HID);    // 10
    agg_v_kernel<HID, 1, 1><<<gWarp1, TPB>>>(q, p, rowstart, edge, inv, b3);          // 11

    // Layer 4: fp32 logits, fused agg+log_softmax
    gemm_bf16_kernel<0, 0, 0><<<gridC, TPB>>>(p, w4t, nullptr, h, NN, HID, NC);       // 12
    agg_lsm_kernel<<<gWarp1, TPB>>>(h, out, rowstart, edge, inv, b4);                 // 13
}